// round 6
// baseline (speedup 1.0000x reference)
#include <cuda_runtime.h>
#include <cuda_bf16.h>
#include <cstdint>

// ============================================================================
// BitLinear: x[4,8192,1024] f32, W[1024,1024] f32, gamma/beta[1024]
// out = (scale_act*alpha) * (Qint @ T^T);  M=32768, K=1024, N=1024
// R6: bf16 HMMA GEMM with CTA tile 256x128, warp tile 64x64 (4 HMMA/LDSM).
// ============================================================================

#define M_ROWS 32768
#define K_DIM  1024
#define N_DIM  1024

// ---------------- device scratch ----------------
__device__ float         g_mu[M_ROWS];
__device__ float         g_rstd[M_ROWS];
__device__ unsigned int  g_absmax_bits;
__device__ float         g_wsum_abs;
__device__ float         g_wsum_absmask;
__device__ float         g_wsum_maskcnt;
__device__ float         g_outscale;
__device__ float         g_qinv;
__device__ __nv_bfloat16 g_qb[(size_t)M_ROWS * K_DIM];   // 64 MB
__device__ __nv_bfloat16 g_tb[(size_t)N_DIM * K_DIM];    // 2 MB

// ---------------- PTX helpers (baseline ISA) --------------------------------
__device__ __forceinline__ uint32_t smem_u32(const void* p) {
    uint32_t a;
    asm("{ .reg .u64 t; cvta.to.shared.u64 t, %1; cvt.u32.u64 %0, t; }"
        : "=r"(a) : "l"(p));
    return a;
}
__device__ __forceinline__ void ldm_x4(uint32_t* r, uint32_t addr) {
    asm volatile("ldmatrix.sync.aligned.m8n8.x4.shared.b16 {%0,%1,%2,%3}, [%4];"
                 : "=r"(r[0]), "=r"(r[1]), "=r"(r[2]), "=r"(r[3]) : "r"(addr));
}
__device__ __forceinline__ void mma_bf16(float* c, const uint32_t* a, const uint32_t* b) {
    asm volatile(
        "mma.sync.aligned.m16n8k16.row.col.f32.bf16.bf16.f32 "
        "{%0,%1,%2,%3}, {%4,%5,%6,%7}, {%8,%9}, {%0,%1,%2,%3};"
        : "+f"(c[0]), "+f"(c[1]), "+f"(c[2]), "+f"(c[3])
        : "r"(a[0]), "r"(a[1]), "r"(a[2]), "r"(a[3]), "r"(b[0]), "r"(b[1]));
}
#define CP_ASYNC16(sm, gm)                                                   \
    asm volatile("cp.async.cg.shared.global [%0], [%1], 16;" ::              \
                 "r"(sm), "l"(__cvta_generic_to_global(gm)))
#define CP_COMMIT() asm volatile("cp.async.commit_group;" ::: "memory")
#define CP_WAIT(n)  asm volatile("cp.async.wait_group %0;" :: "n"(n) : "memory")

// ============================================================================
// Kernel 1: zero accumulators
// ============================================================================
__global__ void zero_kernel() {
    g_absmax_bits  = 0u;
    g_wsum_abs     = 0.0f;
    g_wsum_absmask = 0.0f;
    g_wsum_maskcnt = 0.0f;
}

// ============================================================================
// Kernel 2: LN stats per row + global absmax of normalized output
// ============================================================================
__global__ __launch_bounds__(256) void ln_stats_kernel(
    const float4* __restrict__ x4, const float4* __restrict__ gamma4,
    const float4* __restrict__ beta4) {
    const int row = blockIdx.x;
    const int tid = threadIdx.x;
    float4 v = x4[(size_t)row * 256 + tid];
    float s  = v.x + v.y + v.z + v.w;
    float ss = fmaf(v.x, v.x, fmaf(v.y, v.y, fmaf(v.z, v.z, v.w * v.w)));
#pragma unroll
    for (int o = 16; o > 0; o >>= 1) {
        s  += __shfl_xor_sync(0xffffffffu, s, o);
        ss += __shfl_xor_sync(0xffffffffu, ss, o);
    }
    __shared__ float rs[8], rss[8], bc[2], rm[8];
    const int w = tid >> 5, lane = tid & 31;
    if (lane == 0) { rs[w] = s; rss[w] = ss; }
    __syncthreads();
    if (tid == 0) {
        float ts = 0.f, tss = 0.f;
#pragma unroll
        for (int i = 0; i < 8; ++i) { ts += rs[i]; tss += rss[i]; }
        float mu  = ts * (1.0f / 1024.0f);
        float var = tss * (1.0f / 1024.0f) - mu * mu;
        float rstd = rsqrtf(var + 1e-5f);
        bc[0] = mu; bc[1] = rstd;
        g_mu[row] = mu; g_rstd[row] = rstd;
    }
    __syncthreads();
    const float mu = bc[0], rstd = bc[1];
    float4 g = gamma4[tid], b = beta4[tid];
    float m0 = fabsf(fmaf((v.x - mu) * rstd, g.x, b.x));
    float m1 = fabsf(fmaf((v.y - mu) * rstd, g.y, b.y));
    float m2 = fabsf(fmaf((v.z - mu) * rstd, g.z, b.z));
    float m3 = fabsf(fmaf((v.w - mu) * rstd, g.w, b.w));
    float mm = fmaxf(fmaxf(m0, m1), fmaxf(m2, m3));
#pragma unroll
    for (int o = 16; o > 0; o >>= 1)
        mm = fmaxf(mm, __shfl_xor_sync(0xffffffffu, mm, o));
    if (lane == 0) rm[w] = mm;
    __syncthreads();
    if (tid == 0) {
        float t = rm[0];
#pragma unroll
        for (int i = 1; i < 8; ++i) t = fmaxf(t, rm[i]);
        atomicMax(&g_absmax_bits, __float_as_uint(t));
    }
}

// ============================================================================
// Kernel 3: sum |W|
// ============================================================================
__global__ __launch_bounds__(256) void wabs_kernel(const float4* __restrict__ w4) {
    float s = 0.f;
    for (int i = blockIdx.x * blockDim.x + threadIdx.x; i < (N_DIM * K_DIM / 4);
         i += gridDim.x * blockDim.x) {
        float4 v = w4[i];
        s += fabsf(v.x) + fabsf(v.y) + fabsf(v.z) + fabsf(v.w);
    }
#pragma unroll
    for (int o = 16; o > 0; o >>= 1) s += __shfl_xor_sync(0xffffffffu, s, o);
    __shared__ float rr[8];
    if ((threadIdx.x & 31) == 0) rr[threadIdx.x >> 5] = s;
    __syncthreads();
    if (threadIdx.x == 0) {
        float t = 0.f;
#pragma unroll
        for (int i = 0; i < 8; ++i) t += rr[i];
        atomicAdd(&g_wsum_abs, t);
    }
}

// ============================================================================
// Kernel 4: ternarize W -> bf16 {-1,0,+1}; reduce masked |W| sum + count
// ============================================================================
__global__ __launch_bounds__(256) void wtern_kernel(const float4* __restrict__ w4) {
    const int idx = blockIdx.x * 256 + threadIdx.x;
    const float delta = 0.7f * g_wsum_abs * (1.0f / (float)(N_DIM * K_DIM));
    float4 v = w4[idx];
    float a[4] = {v.x, v.y, v.z, v.w};
    float tf[4];
    float sa = 0.f, cnt = 0.f;
#pragma unroll
    for (int j = 0; j < 4; ++j) {
        float av = fabsf(a[j]);
        if (av > delta) {
            tf[j] = (a[j] > 0.f) ? 1.0f : -1.0f;
            sa += av; cnt += 1.0f;
        } else tf[j] = 0.0f;
    }
    __nv_bfloat162 p0 = __floats2bfloat162_rn(tf[0], tf[1]);
    __nv_bfloat162 p1 = __floats2bfloat162_rn(tf[2], tf[3]);
    uint2 pb;
    pb.x = *reinterpret_cast<uint32_t*>(&p0);
    pb.y = *reinterpret_cast<uint32_t*>(&p1);
    reinterpret_cast<uint2*>(g_tb)[idx] = pb;
#pragma unroll
    for (int o = 16; o > 0; o >>= 1) {
        sa  += __shfl_xor_sync(0xffffffffu, sa, o);
        cnt += __shfl_xor_sync(0xffffffffu, cnt, o);
    }
    __shared__ float ra[8], rc[8];
    if ((threadIdx.x & 31) == 0) { ra[threadIdx.x >> 5] = sa; rc[threadIdx.x >> 5] = cnt; }
    __syncthreads();
    if (threadIdx.x == 0) {
        float ta = 0.f, tc = 0.f;
#pragma unroll
        for (int i = 0; i < 8; ++i) { ta += ra[i]; tc += rc[i]; }
        atomicAdd(&g_wsum_absmask, ta);
        atomicAdd(&g_wsum_maskcnt, tc);
    }
}

// ============================================================================
// Kernel 5: finalize scalars
// ============================================================================
__global__ void finalize_kernel() {
    float amax  = fmaxf(__uint_as_float(g_absmax_bits), 1e-8f);
    float scale = amax * (1.0f / 127.0f);
    float alpha = g_wsum_absmask / fmaxf(g_wsum_maskcnt, 1.0f);
    g_outscale = scale * alpha;
    g_qinv     = 127.0f / amax;
}

// ============================================================================
// Kernel 6: quantize LN(x) -> bf16 integer codes in [-127,127]
// ============================================================================
__global__ __launch_bounds__(256) void quant_kernel(
    const float4* __restrict__ x4, const float4* __restrict__ gamma4,
    const float4* __restrict__ beta4) {
    const int idx = blockIdx.x * 256 + threadIdx.x;
    const int row = idx >> 8;
    const int c4  = idx & 255;
    const float mu = g_mu[row], rstd = g_rstd[row], inv = g_qinv;
    float4 v = x4[idx];
    float4 g = gamma4[c4], b = beta4[c4];
    float q0 = rintf(fminf(fmaxf(fmaf((v.x - mu) * rstd, g.x, b.x) * inv, -127.f), 127.f));
    float q1 = rintf(fminf(fmaxf(fmaf((v.y - mu) * rstd, g.y, b.y) * inv, -127.f), 127.f));
    float q2 = rintf(fminf(fmaxf(fmaf((v.z - mu) * rstd, g.z, b.z) * inv, -127.f), 127.f));
    float q3 = rintf(fminf(fmaxf(fmaf((v.w - mu) * rstd, g.w, b.w) * inv, -127.f), 127.f));
    __nv_bfloat162 p0 = __floats2bfloat162_rn(q0, q1);
    __nv_bfloat162 p1 = __floats2bfloat162_rn(q2, q3);
    uint2 pb;
    pb.x = *reinterpret_cast<uint32_t*>(&p0);
    pb.y = *reinterpret_cast<uint32_t*>(&p1);
    reinterpret_cast<uint2*>(g_qb)[idx] = pb;
}

// ============================================================================
// Kernel 7: bf16 GEMM via mma.sync m16n8k16 (HMMA), f32 accum
// CTA tile 256x128, 8 warps (4M x 2N), warp tile 64x64
// K chunked by 128 B (k64), 3-stage cp.async pipeline, xor-swizzled smem
// stage = A 32KB + B 16KB = 48KB; 3 stages = 144KB smem
// ============================================================================
#define GEMM_STAGES 3
#define A_BYTES     32768
#define B_BYTES     16384
#define STAGE_BYTES (A_BYTES + B_BYTES)
#define GEMM_SMEM   (GEMM_STAGES * STAGE_BYTES)   // 147456; epilogue needs 139264
#define NK_CHUNKS   16

static __device__ __forceinline__ void load_stage(
    const uint8_t* __restrict__ Ag, const uint8_t* __restrict__ Bg,
    uint32_t sA, uint32_t sB, int kt, int tid) {
    const int koff = kt * 128;   // bytes
    // A: 256 rows x 128B = 2048 x 16B -> 8 per thread
#pragma unroll
    for (int i = 0; i < 8; ++i) {
        int v = i * 256 + tid;
        int row = v >> 3, c = v & 7;
        uint32_t sw = (uint32_t)(row * 128 + ((c ^ (row & 7)) << 4));
        size_t go = (size_t)row * (K_DIM * 2) + koff + c * 16;
        CP_ASYNC16(sA + sw, Ag + go);
    }
    // B: 128 rows x 128B = 1024 x 16B -> 4 per thread
#pragma unroll
    for (int i = 0; i < 4; ++i) {
        int v = i * 256 + tid;
        int row = v >> 3, c = v & 7;
        uint32_t sw = (uint32_t)(row * 128 + ((c ^ (row & 7)) << 4));
        size_t go = (size_t)row * (K_DIM * 2) + koff + c * 16;
        CP_ASYNC16(sB + sw, Bg + go);
    }
}

__global__ __launch_bounds__(256, 1) void gemm_kernel(float* __restrict__ out) {
    extern __shared__ char smem[];
    const uint32_t smem_base = smem_u32(smem);
    const int tid = threadIdx.x;
    const int wid = tid >> 5, lane = tid & 31;
    const int warp_m = wid & 3, warp_n = wid >> 2;
    const int m0 = blockIdx.y * 256, n0 = blockIdx.x * 128;

    const uint8_t* Ag = reinterpret_cast<const uint8_t*>(g_qb) + (size_t)m0 * K_DIM * 2;
    const uint8_t* Bg = reinterpret_cast<const uint8_t*>(g_tb) + (size_t)n0 * K_DIM * 2;

    load_stage(Ag, Bg, smem_base, smem_base + A_BYTES, 0, tid);
    CP_COMMIT();
    load_stage(Ag, Bg, smem_base + STAGE_BYTES, smem_base + STAGE_BYTES + A_BYTES, 1, tid);
    CP_COMMIT();

    float C[4][8][4];
#pragma unroll
    for (int i = 0; i < 4; ++i)
#pragma unroll
        for (int j = 0; j < 8; ++j)
#pragma unroll
            for (int k = 0; k < 4; ++k) C[i][j][k] = 0.0f;

    const int rA  = warp_m * 64 + (lane & 15);
    const int cA  = (lane >> 4);
    const int rBo = ((lane & 16) >> 1) + (lane & 7);
    const int cB  = (lane >> 3) & 1;

#pragma unroll 1
    for (int kt = 0; kt < NK_CHUNKS; ++kt) {
        CP_WAIT(1);
        __syncthreads();
        if (kt + 2 < NK_CHUNKS) {
            uint32_t sbase = smem_base + ((kt + 2) % GEMM_STAGES) * STAGE_BYTES;
            load_stage(Ag, Bg, sbase, sbase + A_BYTES, kt + 2, tid);
        }
        CP_COMMIT();

        const uint32_t aB = smem_base + (kt % GEMM_STAGES) * STAGE_BYTES;
        const uint32_t bB = aB + A_BYTES;
#pragma unroll
        for (int ks = 0; ks < 4; ++ks) {         // 4 k16-steps per 128B chunk
            uint32_t a[4][4];
#pragma unroll
            for (int fm = 0; fm < 4; ++fm) {
                int row = rA + fm * 16;
                ldm_x4(a[fm], aB + row * 128 + (((ks * 2 + cA) ^ (row & 7)) << 4));
            }
            uint32_t b[4][4];
#pragma unroll
            for (int p = 0; p < 4; ++p) {
                int row = warp_n * 64 + p * 16 + rBo;
                ldm_x4(b[p], bB + row * 128 + (((ks * 2 + cB) ^ (row & 7)) << 4));
            }
#pragma unroll
            for (int fm = 0; fm < 4; ++fm)
#pragma unroll
                for (int p = 0; p < 4; ++p) {
                    mma_bf16(C[fm][2 * p],     a[fm], &b[p][0]);
                    mma_bf16(C[fm][2 * p + 1], a[fm], &b[p][2]);
                }
        }
        __syncthreads();
    }

    // epilogue: scale, stage through smem (256 rows x stride 136), float4 stores
    const float osc = g_outscale;
    float* stg = reinterpret_cast<float*>(smem);
    __syncthreads();
#pragma unroll
    for (int fm = 0; fm < 4; ++fm) {
        const int rbase = warp_m * 64 + fm * 16 + (lane >> 2);
#pragma unroll
        for (int fn = 0; fn < 8; ++fn) {
            const int col = warp_n * 64 + fn * 8 + (lane & 3) * 2;
            float2 lo, hi;
            lo.x = C[fm][fn][0] * osc;
            lo.y = C[fm][fn][1] * osc;
            hi.x = C[fm][fn][2] * osc;
            hi.y = C[fm][fn][3] * osc;
            *reinterpret_cast<float2*>(&stg[rbase * 136 + col])       = lo;
            *reinterpret_cast<float2*>(&stg[(rbase + 8) * 136 + col]) = hi;
        }
    }
    __syncthreads();
#pragma unroll
    for (int i = 0; i < 32; ++i) {
        int idx = i * 256 + tid;
        int rr = idx >> 5, cc = (idx & 31) * 4;
        float4 vv = *reinterpret_cast<float4*>(&stg[rr * 136 + cc]);
        *reinterpret_cast<float4*>(out + (size_t)(m0 + rr) * N_DIM + n0 + cc) = vv;
    }
}

// ============================================================================
// Launch
// ============================================================================
extern "C" void kernel_launch(void* const* d_in, const int* in_sizes, int n_in,
                              void* d_out, int out_size) {
    const float4* x4 = (const float4*)d_in[0];
    const float4* w4 = (const float4*)d_in[1];
    const float4* g4 = (const float4*)d_in[2];
    const float4* b4 = (const float4*)d_in[3];
    float* out = (float*)d_out;

    zero_kernel<<<1, 1>>>();
    ln_stats_kernel<<<M_ROWS, 256>>>(x4, g4, b4);
    wabs_kernel<<<256, 256>>>(w4);
    wtern_kernel<<<(N_DIM * K_DIM / 4) / 256, 256>>>(w4);
    finalize_kernel<<<1, 1>>>();
    quant_kernel<<<(M_ROWS * K_DIM / 4) / 256, 256>>>(x4, g4, b4);

    static bool attr_set = false;
    if (!attr_set) {
        cudaFuncSetAttribute(gemm_kernel,
                             cudaFuncAttributeMaxDynamicSharedMemorySize, GEMM_SMEM);
        attr_set = true;
    }
    dim3 grid(N_DIM / 128, M_ROWS / 256);
    gemm_kernel<<<grid, 256, GEMM_SMEM>>>(out);
}

// round 7
// speedup vs baseline: 1.0202x; 1.0202x over previous
#include <cuda_runtime.h>
#include <cuda_bf16.h>
#include <cstdint>

// ============================================================================
// BitLinear: x[4,8192,1024] f32, W[1024,1024] f32, gamma/beta[1024]
// out = (scale_act*alpha) * (Qint @ T^T);  M=32768, K=1024, N=1024
// R7: bf16 HMMA GEMM, CTA 256x128 with 512 threads (16 warps, 4Mx4N,
// warp tile 64x32) -> 16 warps/SM like R5 but half the barrier overhead.
// ============================================================================

#define M_ROWS 32768
#define K_DIM  1024
#define N_DIM  1024

// ---------------- device scratch ----------------
__device__ float         g_mu[M_ROWS];
__device__ float         g_rstd[M_ROWS];
__device__ unsigned int  g_absmax_bits;
__device__ float         g_wsum_abs;
__device__ float         g_wsum_absmask;
__device__ float         g_wsum_maskcnt;
__device__ float         g_outscale;
__device__ float         g_qinv;
__device__ __nv_bfloat16 g_qb[(size_t)M_ROWS * K_DIM];   // 64 MB
__device__ __nv_bfloat16 g_tb[(size_t)N_DIM * K_DIM];    // 2 MB

// ---------------- PTX helpers (baseline ISA) --------------------------------
__device__ __forceinline__ uint32_t smem_u32(const void* p) {
    uint32_t a;
    asm("{ .reg .u64 t; cvta.to.shared.u64 t, %1; cvt.u32.u64 %0, t; }"
        : "=r"(a) : "l"(p));
    return a;
}
__device__ __forceinline__ void ldm_x4(uint32_t* r, uint32_t addr) {
    asm volatile("ldmatrix.sync.aligned.m8n8.x4.shared.b16 {%0,%1,%2,%3}, [%4];"
                 : "=r"(r[0]), "=r"(r[1]), "=r"(r[2]), "=r"(r[3]) : "r"(addr));
}
__device__ __forceinline__ void mma_bf16(float* c, const uint32_t* a, const uint32_t* b) {
    asm volatile(
        "mma.sync.aligned.m16n8k16.row.col.f32.bf16.bf16.f32 "
        "{%0,%1,%2,%3}, {%4,%5,%6,%7}, {%8,%9}, {%0,%1,%2,%3};"
        : "+f"(c[0]), "+f"(c[1]), "+f"(c[2]), "+f"(c[3])
        : "r"(a[0]), "r"(a[1]), "r"(a[2]), "r"(a[3]), "r"(b[0]), "r"(b[1]));
}
#define CP_ASYNC16(sm, gm)                                                   \
    asm volatile("cp.async.cg.shared.global [%0], [%1], 16;" ::              \
                 "r"(sm), "l"(__cvta_generic_to_global(gm)))
#define CP_COMMIT() asm volatile("cp.async.commit_group;" ::: "memory")
#define CP_WAIT(n)  asm volatile("cp.async.wait_group %0;" :: "n"(n) : "memory")

// ============================================================================
// Kernel 1: zero accumulators
// ============================================================================
__global__ void zero_kernel() {
    g_absmax_bits  = 0u;
    g_wsum_abs     = 0.0f;
    g_wsum_absmask = 0.0f;
    g_wsum_maskcnt = 0.0f;
}

// ============================================================================
// Kernel 2: LN stats per row + global absmax of normalized output
// ============================================================================
__global__ __launch_bounds__(256) void ln_stats_kernel(
    const float4* __restrict__ x4, const float4* __restrict__ gamma4,
    const float4* __restrict__ beta4) {
    const int row = blockIdx.x;
    const int tid = threadIdx.x;
    float4 v = x4[(size_t)row * 256 + tid];
    float s  = v.x + v.y + v.z + v.w;
    float ss = fmaf(v.x, v.x, fmaf(v.y, v.y, fmaf(v.z, v.z, v.w * v.w)));
#pragma unroll
    for (int o = 16; o > 0; o >>= 1) {
        s  += __shfl_xor_sync(0xffffffffu, s, o);
        ss += __shfl_xor_sync(0xffffffffu, ss, o);
    }
    __shared__ float rs[8], rss[8], bc[2], rm[8];
    const int w = tid >> 5, lane = tid & 31;
    if (lane == 0) { rs[w] = s; rss[w] = ss; }
    __syncthreads();
    if (tid == 0) {
        float ts = 0.f, tss = 0.f;
#pragma unroll
        for (int i = 0; i < 8; ++i) { ts += rs[i]; tss += rss[i]; }
        float mu  = ts * (1.0f / 1024.0f);
        float var = tss * (1.0f / 1024.0f) - mu * mu;
        float rstd = rsqrtf(var + 1e-5f);
        bc[0] = mu; bc[1] = rstd;
        g_mu[row] = mu; g_rstd[row] = rstd;
    }
    __syncthreads();
    const float mu = bc[0], rstd = bc[1];
    float4 g = gamma4[tid], b = beta4[tid];
    float m0 = fabsf(fmaf((v.x - mu) * rstd, g.x, b.x));
    float m1 = fabsf(fmaf((v.y - mu) * rstd, g.y, b.y));
    float m2 = fabsf(fmaf((v.z - mu) * rstd, g.z, b.z));
    float m3 = fabsf(fmaf((v.w - mu) * rstd, g.w, b.w));
    float mm = fmaxf(fmaxf(m0, m1), fmaxf(m2, m3));
#pragma unroll
    for (int o = 16; o > 0; o >>= 1)
        mm = fmaxf(mm, __shfl_xor_sync(0xffffffffu, mm, o));
    if (lane == 0) rm[w] = mm;
    __syncthreads();
    if (tid == 0) {
        float t = rm[0];
#pragma unroll
        for (int i = 1; i < 8; ++i) t = fmaxf(t, rm[i]);
        atomicMax(&g_absmax_bits, __float_as_uint(t));
    }
}

// ============================================================================
// Kernel 3: sum |W|
// ============================================================================
__global__ __launch_bounds__(256) void wabs_kernel(const float4* __restrict__ w4) {
    float s = 0.f;
    for (int i = blockIdx.x * blockDim.x + threadIdx.x; i < (N_DIM * K_DIM / 4);
         i += gridDim.x * blockDim.x) {
        float4 v = w4[i];
        s += fabsf(v.x) + fabsf(v.y) + fabsf(v.z) + fabsf(v.w);
    }
#pragma unroll
    for (int o = 16; o > 0; o >>= 1) s += __shfl_xor_sync(0xffffffffu, s, o);
    __shared__ float rr[8];
    if ((threadIdx.x & 31) == 0) rr[threadIdx.x >> 5] = s;
    __syncthreads();
    if (threadIdx.x == 0) {
        float t = 0.f;
#pragma unroll
        for (int i = 0; i < 8; ++i) t += rr[i];
        atomicAdd(&g_wsum_abs, t);
    }
}

// ============================================================================
// Kernel 4: ternarize W -> bf16 {-1,0,+1}; reduce masked |W| sum + count
// ============================================================================
__global__ __launch_bounds__(256) void wtern_kernel(const float4* __restrict__ w4) {
    const int idx = blockIdx.x * 256 + threadIdx.x;
    const float delta = 0.7f * g_wsum_abs * (1.0f / (float)(N_DIM * K_DIM));
    float4 v = w4[idx];
    float a[4] = {v.x, v.y, v.z, v.w};
    float tf[4];
    float sa = 0.f, cnt = 0.f;
#pragma unroll
    for (int j = 0; j < 4; ++j) {
        float av = fabsf(a[j]);
        if (av > delta) {
            tf[j] = (a[j] > 0.f) ? 1.0f : -1.0f;
            sa += av; cnt += 1.0f;
        } else tf[j] = 0.0f;
    }
    __nv_bfloat162 p0 = __floats2bfloat162_rn(tf[0], tf[1]);
    __nv_bfloat162 p1 = __floats2bfloat162_rn(tf[2], tf[3]);
    uint2 pb;
    pb.x = *reinterpret_cast<uint32_t*>(&p0);
    pb.y = *reinterpret_cast<uint32_t*>(&p1);
    reinterpret_cast<uint2*>(g_tb)[idx] = pb;
#pragma unroll
    for (int o = 16; o > 0; o >>= 1) {
        sa  += __shfl_xor_sync(0xffffffffu, sa, o);
        cnt += __shfl_xor_sync(0xffffffffu, cnt, o);
    }
    __shared__ float ra[8], rc[8];
    if ((threadIdx.x & 31) == 0) { ra[threadIdx.x >> 5] = sa; rc[threadIdx.x >> 5] = cnt; }
    __syncthreads();
    if (threadIdx.x == 0) {
        float ta = 0.f, tc = 0.f;
#pragma unroll
        for (int i = 0; i < 8; ++i) { ta += ra[i]; tc += rc[i]; }
        atomicAdd(&g_wsum_absmask, ta);
        atomicAdd(&g_wsum_maskcnt, tc);
    }
}

// ============================================================================
// Kernel 5: finalize scalars
// ============================================================================
__global__ void finalize_kernel() {
    float amax  = fmaxf(__uint_as_float(g_absmax_bits), 1e-8f);
    float scale = amax * (1.0f / 127.0f);
    float alpha = g_wsum_absmask / fmaxf(g_wsum_maskcnt, 1.0f);
    g_outscale = scale * alpha;
    g_qinv     = 127.0f / amax;
}

// ============================================================================
// Kernel 6: quantize LN(x) -> bf16 integer codes in [-127,127]
// ============================================================================
__global__ __launch_bounds__(256) void quant_kernel(
    const float4* __restrict__ x4, const float4* __restrict__ gamma4,
    const float4* __restrict__ beta4) {
    const int idx = blockIdx.x * 256 + threadIdx.x;
    const int row = idx >> 8;
    const int c4  = idx & 255;
    const float mu = g_mu[row], rstd = g_rstd[row], inv = g_qinv;
    float4 v = x4[idx];
    float4 g = gamma4[c4], b = beta4[c4];
    float q0 = rintf(fminf(fmaxf(fmaf((v.x - mu) * rstd, g.x, b.x) * inv, -127.f), 127.f));
    float q1 = rintf(fminf(fmaxf(fmaf((v.y - mu) * rstd, g.y, b.y) * inv, -127.f), 127.f));
    float q2 = rintf(fminf(fmaxf(fmaf((v.z - mu) * rstd, g.z, b.z) * inv, -127.f), 127.f));
    float q3 = rintf(fminf(fmaxf(fmaf((v.w - mu) * rstd, g.w, b.w) * inv, -127.f), 127.f));
    __nv_bfloat162 p0 = __floats2bfloat162_rn(q0, q1);
    __nv_bfloat162 p1 = __floats2bfloat162_rn(q2, q3);
    uint2 pb;
    pb.x = *reinterpret_cast<uint32_t*>(&p0);
    pb.y = *reinterpret_cast<uint32_t*>(&p1);
    reinterpret_cast<uint2*>(g_qb)[idx] = pb;
}

// ============================================================================
// Kernel 7: bf16 GEMM via mma.sync m16n8k16 (HMMA), f32 accum
// CTA tile 256x128, 512 threads = 16 warps (4M x 4N), warp tile 64x32
// K chunked by 128 B (k64), 3-stage cp.async pipeline, xor-swizzled smem
// stage = A 32KB + B 16KB = 48KB; 3 stages = 144KB smem, 1 CTA/SM, 16 warps
// ============================================================================
#define GEMM_STAGES 3
#define A_BYTES     32768
#define B_BYTES     16384
#define STAGE_BYTES (A_BYTES + B_BYTES)
#define GEMM_SMEM   (GEMM_STAGES * STAGE_BYTES)   // 147456; epilogue needs 139264
#define NK_CHUNKS   16

static __device__ __forceinline__ void load_stage(
    const uint8_t* __restrict__ Ag, const uint8_t* __restrict__ Bg,
    uint32_t sA, uint32_t sB, int kt, int tid) {
    const int koff = kt * 128;   // bytes
    // A: 256 rows x 128B = 2048 x 16B -> 4 per thread (512 thr)
#pragma unroll
    for (int i = 0; i < 4; ++i) {
        int v = i * 512 + tid;
        int row = v >> 3, c = v & 7;
        uint32_t sw = (uint32_t)(row * 128 + ((c ^ (row & 7)) << 4));
        size_t go = (size_t)row * (K_DIM * 2) + koff + c * 16;
        CP_ASYNC16(sA + sw, Ag + go);
    }
    // B: 128 rows x 128B = 1024 x 16B -> 2 per thread
#pragma unroll
    for (int i = 0; i < 2; ++i) {
        int v = i * 512 + tid;
        int row = v >> 3, c = v & 7;
        uint32_t sw = (uint32_t)(row * 128 + ((c ^ (row & 7)) << 4));
        size_t go = (size_t)row * (K_DIM * 2) + koff + c * 16;
        CP_ASYNC16(sB + sw, Bg + go);
    }
}

__global__ __launch_bounds__(512, 1) void gemm_kernel(float* __restrict__ out) {
    extern __shared__ char smem[];
    const uint32_t smem_base = smem_u32(smem);
    const int tid = threadIdx.x;
    const int wid = tid >> 5, lane = tid & 31;
    const int warp_m = wid & 3, warp_n = wid >> 2;   // 4 x 4
    const int m0 = blockIdx.y * 256, n0 = blockIdx.x * 128;

    const uint8_t* Ag = reinterpret_cast<const uint8_t*>(g_qb) + (size_t)m0 * K_DIM * 2;
    const uint8_t* Bg = reinterpret_cast<const uint8_t*>(g_tb) + (size_t)n0 * K_DIM * 2;

    load_stage(Ag, Bg, smem_base, smem_base + A_BYTES, 0, tid);
    CP_COMMIT();
    load_stage(Ag, Bg, smem_base + STAGE_BYTES, smem_base + STAGE_BYTES + A_BYTES, 1, tid);
    CP_COMMIT();

    float C[4][4][4];
#pragma unroll
    for (int i = 0; i < 4; ++i)
#pragma unroll
        for (int j = 0; j < 4; ++j)
#pragma unroll
            for (int k = 0; k < 4; ++k) C[i][j][k] = 0.0f;

    const int rA  = warp_m * 64 + (lane & 15);
    const int cA  = (lane >> 4);
    const int rBo = ((lane & 16) >> 1) + (lane & 7);
    const int cB  = (lane >> 3) & 1;

#pragma unroll 1
    for (int kt = 0; kt < NK_CHUNKS; ++kt) {
        CP_WAIT(1);
        __syncthreads();
        if (kt + 2 < NK_CHUNKS) {
            uint32_t sbase = smem_base + ((kt + 2) % GEMM_STAGES) * STAGE_BYTES;
            load_stage(Ag, Bg, sbase, sbase + A_BYTES, kt + 2, tid);
        }
        CP_COMMIT();

        const uint32_t aB = smem_base + (kt % GEMM_STAGES) * STAGE_BYTES;
        const uint32_t bB = aB + A_BYTES;
#pragma unroll
        for (int ks = 0; ks < 4; ++ks) {         // 4 k16-steps per 128B chunk
            uint32_t a[4][4];
#pragma unroll
            for (int fm = 0; fm < 4; ++fm) {
                int row = rA + fm * 16;
                ldm_x4(a[fm], aB + row * 128 + (((ks * 2 + cA) ^ (row & 7)) << 4));
            }
            uint32_t b[2][4];
#pragma unroll
            for (int p = 0; p < 2; ++p) {
                int row = warp_n * 32 + p * 16 + rBo;
                ldm_x4(b[p], bB + row * 128 + (((ks * 2 + cB) ^ (row & 7)) << 4));
            }
#pragma unroll
            for (int fm = 0; fm < 4; ++fm)
#pragma unroll
                for (int p = 0; p < 2; ++p) {
                    mma_bf16(C[fm][2 * p],     a[fm], &b[p][0]);
                    mma_bf16(C[fm][2 * p + 1], a[fm], &b[p][2]);
                }
        }
        __syncthreads();
    }

    // epilogue: scale, stage through smem (256 rows x stride 136), float4 stores
    const float osc = g_outscale;
    float* stg = reinterpret_cast<float*>(smem);
    __syncthreads();
#pragma unroll
    for (int fm = 0; fm < 4; ++fm) {
        const int rbase = warp_m * 64 + fm * 16 + (lane >> 2);
#pragma unroll
        for (int fn = 0; fn < 4; ++fn) {
            const int col = warp_n * 32 + fn * 8 + (lane & 3) * 2;
            float2 lo, hi;
            lo.x = C[fm][fn][0] * osc;
            lo.y = C[fm][fn][1] * osc;
            hi.x = C[fm][fn][2] * osc;
            hi.y = C[fm][fn][3] * osc;
            *reinterpret_cast<float2*>(&stg[rbase * 136 + col])       = lo;
            *reinterpret_cast<float2*>(&stg[(rbase + 8) * 136 + col]) = hi;
        }
    }
    __syncthreads();
#pragma unroll
    for (int i = 0; i < 16; ++i) {
        int idx = i * 512 + tid;
        int rr = idx >> 5, cc = (idx & 31) * 4;
        float4 vv = *reinterpret_cast<float4*>(&stg[rr * 136 + cc]);
        *reinterpret_cast<float4*>(out + (size_t)(m0 + rr) * N_DIM + n0 + cc) = vv;
    }
}

// ============================================================================
// Launch
// ============================================================================
extern "C" void kernel_launch(void* const* d_in, const int* in_sizes, int n_in,
                              void* d_out, int out_size) {
    const float4* x4 = (const float4*)d_in[0];
    const float4* w4 = (const float4*)d_in[1];
    const float4* g4 = (const float4*)d_in[2];
    const float4* b4 = (const float4*)d_in[3];
    float* out = (float*)d_out;

    zero_kernel<<<1, 1>>>();
    ln_stats_kernel<<<M_ROWS, 256>>>(x4, g4, b4);
    wabs_kernel<<<256, 256>>>(w4);
    wtern_kernel<<<(N_DIM * K_DIM / 4) / 256, 256>>>(w4);
    finalize_kernel<<<1, 1>>>();
    quant_kernel<<<(M_ROWS * K_DIM / 4) / 256, 256>>>(x4, g4, b4);

    static bool attr_set = false;
    if (!attr_set) {
        cudaFuncSetAttribute(gemm_kernel,
                             cudaFuncAttributeMaxDynamicSharedMemorySize, GEMM_SMEM);
        attr_set = true;
    }
    dim3 grid(N_DIM / 128, M_ROWS / 256);
    gemm_kernel<<<grid, 512, GEMM_SMEM>>>(out);
}

// round 8
// speedup vs baseline: 1.0943x; 1.0726x over previous
#include <cuda_runtime.h>
#include <cuda_bf16.h>
#include <cstdint>

// ============================================================================
// BitLinear: x[4,8192,1024] f32, W[1024,1024] f32, gamma/beta[1024]
// out = (scale_act*alpha) * (Qint @ T^T);  M=32768, K=1024, N=1024
// R8: R5 GEMM config (128x128, 8 warps, 2 CTAs/SM) + single-sync mainloop
//     + direct-store epilogue (no smem staging).
// ============================================================================

#define M_ROWS 32768
#define K_DIM  1024
#define N_DIM  1024

// ---------------- device scratch ----------------
__device__ float         g_mu[M_ROWS];
__device__ float         g_rstd[M_ROWS];
__device__ unsigned int  g_absmax_bits;
__device__ float         g_wsum_abs;
__device__ float         g_wsum_absmask;
__device__ float         g_wsum_maskcnt;
__device__ float         g_outscale;
__device__ float         g_qinv;
__device__ __nv_bfloat16 g_qb[(size_t)M_ROWS * K_DIM];   // 64 MB
__device__ __nv_bfloat16 g_tb[(size_t)N_DIM * K_DIM];    // 2 MB

// ---------------- PTX helpers (baseline ISA) --------------------------------
__device__ __forceinline__ uint32_t smem_u32(const void* p) {
    uint32_t a;
    asm("{ .reg .u64 t; cvta.to.shared.u64 t, %1; cvt.u32.u64 %0, t; }"
        : "=r"(a) : "l"(p));
    return a;
}
__device__ __forceinline__ void ldm_x4(uint32_t* r, uint32_t addr) {
    asm volatile("ldmatrix.sync.aligned.m8n8.x4.shared.b16 {%0,%1,%2,%3}, [%4];"
                 : "=r"(r[0]), "=r"(r[1]), "=r"(r[2]), "=r"(r[3]) : "r"(addr));
}
__device__ __forceinline__ void mma_bf16(float* c, const uint32_t* a, const uint32_t* b) {
    asm volatile(
        "mma.sync.aligned.m16n8k16.row.col.f32.bf16.bf16.f32 "
        "{%0,%1,%2,%3}, {%4,%5,%6,%7}, {%8,%9}, {%0,%1,%2,%3};"
        : "+f"(c[0]), "+f"(c[1]), "+f"(c[2]), "+f"(c[3])
        : "r"(a[0]), "r"(a[1]), "r"(a[2]), "r"(a[3]), "r"(b[0]), "r"(b[1]));
}
#define CP_ASYNC16(sm, gm)                                                   \
    asm volatile("cp.async.cg.shared.global [%0], [%1], 16;" ::              \
                 "r"(sm), "l"(__cvta_generic_to_global(gm)))
#define CP_COMMIT() asm volatile("cp.async.commit_group;" ::: "memory")
#define CP_WAIT(n)  asm volatile("cp.async.wait_group %0;" :: "n"(n) : "memory")

// ============================================================================
// Kernel 1: zero accumulators
// ============================================================================
__global__ void zero_kernel() {
    g_absmax_bits  = 0u;
    g_wsum_abs     = 0.0f;
    g_wsum_absmask = 0.0f;
    g_wsum_maskcnt = 0.0f;
}

// ============================================================================
// Kernel 2: LN stats per row + global absmax of normalized output
// ============================================================================
__global__ __launch_bounds__(256) void ln_stats_kernel(
    const float4* __restrict__ x4, const float4* __restrict__ gamma4,
    const float4* __restrict__ beta4) {
    const int row = blockIdx.x;
    const int tid = threadIdx.x;
    float4 v = x4[(size_t)row * 256 + tid];
    float s  = v.x + v.y + v.z + v.w;
    float ss = fmaf(v.x, v.x, fmaf(v.y, v.y, fmaf(v.z, v.z, v.w * v.w)));
#pragma unroll
    for (int o = 16; o > 0; o >>= 1) {
        s  += __shfl_xor_sync(0xffffffffu, s, o);
        ss += __shfl_xor_sync(0xffffffffu, ss, o);
    }
    __shared__ float rs[8], rss[8], bc[2], rm[8];
    const int w = tid >> 5, lane = tid & 31;
    if (lane == 0) { rs[w] = s; rss[w] = ss; }
    __syncthreads();
    if (tid == 0) {
        float ts = 0.f, tss = 0.f;
#pragma unroll
        for (int i = 0; i < 8; ++i) { ts += rs[i]; tss += rss[i]; }
        float mu  = ts * (1.0f / 1024.0f);
        float var = tss * (1.0f / 1024.0f) - mu * mu;
        float rstd = rsqrtf(var + 1e-5f);
        bc[0] = mu; bc[1] = rstd;
        g_mu[row] = mu; g_rstd[row] = rstd;
    }
    __syncthreads();
    const float mu = bc[0], rstd = bc[1];
    float4 g = gamma4[tid], b = beta4[tid];
    float m0 = fabsf(fmaf((v.x - mu) * rstd, g.x, b.x));
    float m1 = fabsf(fmaf((v.y - mu) * rstd, g.y, b.y));
    float m2 = fabsf(fmaf((v.z - mu) * rstd, g.z, b.z));
    float m3 = fabsf(fmaf((v.w - mu) * rstd, g.w, b.w));
    float mm = fmaxf(fmaxf(m0, m1), fmaxf(m2, m3));
#pragma unroll
    for (int o = 16; o > 0; o >>= 1)
        mm = fmaxf(mm, __shfl_xor_sync(0xffffffffu, mm, o));
    if (lane == 0) rm[w] = mm;
    __syncthreads();
    if (tid == 0) {
        float t = rm[0];
#pragma unroll
        for (int i = 1; i < 8; ++i) t = fmaxf(t, rm[i]);
        atomicMax(&g_absmax_bits, __float_as_uint(t));
    }
}

// ============================================================================
// Kernel 3: sum |W|
// ============================================================================
__global__ __launch_bounds__(256) void wabs_kernel(const float4* __restrict__ w4) {
    float s = 0.f;
    for (int i = blockIdx.x * blockDim.x + threadIdx.x; i < (N_DIM * K_DIM / 4);
         i += gridDim.x * blockDim.x) {
        float4 v = w4[i];
        s += fabsf(v.x) + fabsf(v.y) + fabsf(v.z) + fabsf(v.w);
    }
#pragma unroll
    for (int o = 16; o > 0; o >>= 1) s += __shfl_xor_sync(0xffffffffu, s, o);
    __shared__ float rr[8];
    if ((threadIdx.x & 31) == 0) rr[threadIdx.x >> 5] = s;
    __syncthreads();
    if (threadIdx.x == 0) {
        float t = 0.f;
#pragma unroll
        for (int i = 0; i < 8; ++i) t += rr[i];
        atomicAdd(&g_wsum_abs, t);
    }
}

// ============================================================================
// Kernel 4: ternarize W -> bf16 {-1,0,+1}; reduce masked |W| sum + count
// ============================================================================
__global__ __launch_bounds__(256) void wtern_kernel(const float4* __restrict__ w4) {
    const int idx = blockIdx.x * 256 + threadIdx.x;
    const float delta = 0.7f * g_wsum_abs * (1.0f / (float)(N_DIM * K_DIM));
    float4 v = w4[idx];
    float a[4] = {v.x, v.y, v.z, v.w};
    float tf[4];
    float sa = 0.f, cnt = 0.f;
#pragma unroll
    for (int j = 0; j < 4; ++j) {
        float av = fabsf(a[j]);
        if (av > delta) {
            tf[j] = (a[j] > 0.f) ? 1.0f : -1.0f;
            sa += av; cnt += 1.0f;
        } else tf[j] = 0.0f;
    }
    __nv_bfloat162 p0 = __floats2bfloat162_rn(tf[0], tf[1]);
    __nv_bfloat162 p1 = __floats2bfloat162_rn(tf[2], tf[3]);
    uint2 pb;
    pb.x = *reinterpret_cast<uint32_t*>(&p0);
    pb.y = *reinterpret_cast<uint32_t*>(&p1);
    reinterpret_cast<uint2*>(g_tb)[idx] = pb;
#pragma unroll
    for (int o = 16; o > 0; o >>= 1) {
        sa  += __shfl_xor_sync(0xffffffffu, sa, o);
        cnt += __shfl_xor_sync(0xffffffffu, cnt, o);
    }
    __shared__ float ra[8], rc[8];
    if ((threadIdx.x & 31) == 0) { ra[threadIdx.x >> 5] = sa; rc[threadIdx.x >> 5] = cnt; }
    __syncthreads();
    if (threadIdx.x == 0) {
        float ta = 0.f, tc = 0.f;
#pragma unroll
        for (int i = 0; i < 8; ++i) { ta += ra[i]; tc += rc[i]; }
        atomicAdd(&g_wsum_absmask, ta);
        atomicAdd(&g_wsum_maskcnt, tc);
    }
}

// ============================================================================
// Kernel 5: finalize scalars
// ============================================================================
__global__ void finalize_kernel() {
    float amax  = fmaxf(__uint_as_float(g_absmax_bits), 1e-8f);
    float scale = amax * (1.0f / 127.0f);
    float alpha = g_wsum_absmask / fmaxf(g_wsum_maskcnt, 1.0f);
    g_outscale = scale * alpha;
    g_qinv     = 127.0f / amax;
}

// ============================================================================
// Kernel 6: quantize LN(x) -> bf16 integer codes in [-127,127]
// ============================================================================
__global__ __launch_bounds__(256) void quant_kernel(
    const float4* __restrict__ x4, const float4* __restrict__ gamma4,
    const float4* __restrict__ beta4) {
    const int idx = blockIdx.x * 256 + threadIdx.x;
    const int row = idx >> 8;
    const int c4  = idx & 255;
    const float mu = g_mu[row], rstd = g_rstd[row], inv = g_qinv;
    float4 v = x4[idx];
    float4 g = gamma4[c4], b = beta4[c4];
    float q0 = rintf(fminf(fmaxf(fmaf((v.x - mu) * rstd, g.x, b.x) * inv, -127.f), 127.f));
    float q1 = rintf(fminf(fmaxf(fmaf((v.y - mu) * rstd, g.y, b.y) * inv, -127.f), 127.f));
    float q2 = rintf(fminf(fmaxf(fmaf((v.z - mu) * rstd, g.z, b.z) * inv, -127.f), 127.f));
    float q3 = rintf(fminf(fmaxf(fmaf((v.w - mu) * rstd, g.w, b.w) * inv, -127.f), 127.f));
    __nv_bfloat162 p0 = __floats2bfloat162_rn(q0, q1);
    __nv_bfloat162 p1 = __floats2bfloat162_rn(q2, q3);
    uint2 pb;
    pb.x = *reinterpret_cast<uint32_t*>(&p0);
    pb.y = *reinterpret_cast<uint32_t*>(&p1);
    reinterpret_cast<uint2*>(g_qb)[idx] = pb;
}

// ============================================================================
// Kernel 7: bf16 GEMM via mma.sync m16n8k16 (HMMA), f32 accum
// CTA tile 128x128, 8 warps (4M x 2N), warp tile 32x64
// K chunked by 128 B (k64), 3-stage cp.async pipeline, xor-swizzled smem
// ONE __syncthreads per mainloop iteration; direct-store epilogue.
// ============================================================================
#define GEMM_STAGES 3
#define STAGE_BYTES 32768
#define GEMM_SMEM   (GEMM_STAGES * STAGE_BYTES)
#define NK_CHUNKS   16

static __device__ __forceinline__ void load_stage(
    const uint8_t* __restrict__ Ag, const uint8_t* __restrict__ Bg,
    uint32_t sA, uint32_t sB, int kt, int tid) {
    const int koff = kt * 128;   // bytes
#pragma unroll
    for (int i = 0; i < 4; ++i) {
        int v = i * 256 + tid;
        int row = v >> 3, c = v & 7;
        uint32_t sw = (uint32_t)(row * 128 + ((c ^ (row & 7)) << 4));
        size_t go = (size_t)row * (K_DIM * 2) + koff + c * 16;
        CP_ASYNC16(sA + sw, Ag + go);
        CP_ASYNC16(sB + sw, Bg + go);
    }
}

__global__ __launch_bounds__(256, 2) void gemm_kernel(float* __restrict__ out) {
    extern __shared__ char smem[];
    const uint32_t smem_base = smem_u32(smem);
    const int tid = threadIdx.x;
    const int wid = tid >> 5, lane = tid & 31;
    const int warp_m = wid & 3, warp_n = wid >> 2;
    const int m0 = blockIdx.y * 128, n0 = blockIdx.x * 128;

    const uint8_t* Ag = reinterpret_cast<const uint8_t*>(g_qb) + (size_t)m0 * K_DIM * 2;
    const uint8_t* Bg = reinterpret_cast<const uint8_t*>(g_tb) + (size_t)n0 * K_DIM * 2;

    load_stage(Ag, Bg, smem_base, smem_base + 16384, 0, tid);
    CP_COMMIT();
    load_stage(Ag, Bg, smem_base + STAGE_BYTES, smem_base + STAGE_BYTES + 16384, 1, tid);
    CP_COMMIT();

    float C[2][8][4];
#pragma unroll
    for (int i = 0; i < 2; ++i)
#pragma unroll
        for (int j = 0; j < 8; ++j)
#pragma unroll
            for (int k = 0; k < 4; ++k) C[i][j][k] = 0.0f;

    const int rA  = warp_m * 32 + (lane & 15);
    const int cA  = (lane >> 4);
    const int rBo = ((lane & 16) >> 1) + (lane & 7);
    const int cB  = (lane >> 3) & 1;

#pragma unroll 1
    for (int kt = 0; kt < NK_CHUNKS; ++kt) {
        CP_WAIT(1);
        __syncthreads();   // single barrier per iteration:
                           // stage (kt+2)%3's last readers ran in iter kt-1,
                           // which all threads completed before this barrier.
        if (kt + 2 < NK_CHUNKS) {
            uint32_t sbase = smem_base + ((kt + 2) % GEMM_STAGES) * STAGE_BYTES;
            load_stage(Ag, Bg, sbase, sbase + 16384, kt + 2, tid);
        }
        CP_COMMIT();

        const uint32_t aB = smem_base + (kt % GEMM_STAGES) * STAGE_BYTES;
        const uint32_t bB = aB + 16384;
#pragma unroll
        for (int ks = 0; ks < 4; ++ks) {         // 4 k16-steps per 128B chunk
            uint32_t a[2][4];
#pragma unroll
            for (int fm = 0; fm < 2; ++fm) {
                int row = rA + fm * 16;
                ldm_x4(a[fm], aB + row * 128 + (((ks * 2 + cA) ^ (row & 7)) << 4));
            }
            uint32_t b[4][4];
#pragma unroll
            for (int p = 0; p < 4; ++p) {
                int row = warp_n * 64 + p * 16 + rBo;
                ldm_x4(b[p], bB + row * 128 + (((ks * 2 + cB) ^ (row & 7)) << 4));
            }
#pragma unroll
            for (int fm = 0; fm < 2; ++fm)
#pragma unroll
                for (int p = 0; p < 4; ++p) {
                    mma_bf16(C[fm][2 * p],     a[fm], &b[p][0]);
                    mma_bf16(C[fm][2 * p + 1], a[fm], &b[p][2]);
                }
        }
    }

    // ---------------- epilogue: direct float2 stores -------------------------
    // fragment (fm, fn, {0,1,2,3}): rows warp_m*32+fm*16+(lane>>2)(+8),
    // cols warp_n*64+fn*8+(lane&3)*2 (+1). 4 lanes cover one 32B sector.
    const float osc = g_outscale;
#pragma unroll
    for (int fm = 0; fm < 2; ++fm) {
        const int r0 = m0 + warp_m * 32 + fm * 16 + (lane >> 2);
#pragma unroll
        for (int fn = 0; fn < 8; ++fn) {
            const int col = n0 + warp_n * 64 + fn * 8 + (lane & 3) * 2;
            float2 lo, hi;
            lo.x = C[fm][fn][0] * osc;
            lo.y = C[fm][fn][1] * osc;
            hi.x = C[fm][fn][2] * osc;
            hi.y = C[fm][fn][3] * osc;
            *reinterpret_cast<float2*>(out + (size_t)r0 * N_DIM + col)       = lo;
            *reinterpret_cast<float2*>(out + (size_t)(r0 + 8) * N_DIM + col) = hi;
        }
    }
}

// ============================================================================
// Launch
// ============================================================================
extern "C" void kernel_launch(void* const* d_in, const int* in_sizes, int n_in,
                              void* d_out, int out_size) {
    const float4* x4 = (const float4*)d_in[0];
    const float4* w4 = (const float4*)d_in[1];
    const float4* g4 = (const float4*)d_in[2];
    const float4* b4 = (const float4*)d_in[3];
    float* out = (float*)d_out;

    zero_kernel<<<1, 1>>>();
    ln_stats_kernel<<<M_ROWS, 256>>>(x4, g4, b4);
    wabs_kernel<<<256, 256>>>(w4);
    wtern_kernel<<<(N_DIM * K_DIM / 4) / 256, 256>>>(w4);
    finalize_kernel<<<1, 1>>>();
    quant_kernel<<<(M_ROWS * K_DIM / 4) / 256, 256>>>(x4, g4, b4);

    static bool attr_set = false;
    if (!attr_set) {
        cudaFuncSetAttribute(gemm_kernel,
                             cudaFuncAttributeMaxDynamicSharedMemorySize, GEMM_SMEM);
        attr_set = true;
    }
    dim3 grid(N_DIM / 128, M_ROWS / 128);
    gemm_kernel<<<grid, 256, GEMM_SMEM>>>(out);
}

// round 9
// speedup vs baseline: 1.1110x; 1.0152x over previous
#include <cuda_runtime.h>
#include <cuda_bf16.h>
#include <cstdint>

// ============================================================================
// BitLinear: x[4,8192,1024] f32, W[1024,1024] f32, gamma/beta[1024]
// out = (scale_act*alpha) * (Qint @ T^T);  M=32768, K=1024, N=1024
// R9: GEMM CTA 128x128 with 128 threads (4 warps, 2Mx2N, warp tile 64x64)
//     -> 0.094 B/MAC smem traffic (was 0.125) while keeping 2 CTAs/SM.
// ============================================================================

#define M_ROWS 32768
#define K_DIM  1024
#define N_DIM  1024

// ---------------- device scratch ----------------
__device__ float         g_mu[M_ROWS];
__device__ float         g_rstd[M_ROWS];
__device__ unsigned int  g_absmax_bits;
__device__ float         g_wsum_abs;
__device__ float         g_wsum_absmask;
__device__ float         g_wsum_maskcnt;
__device__ float         g_outscale;
__device__ float         g_qinv;
__device__ __nv_bfloat16 g_qb[(size_t)M_ROWS * K_DIM];   // 64 MB
__device__ __nv_bfloat16 g_tb[(size_t)N_DIM * K_DIM];    // 2 MB

// ---------------- PTX helpers (baseline ISA) --------------------------------
__device__ __forceinline__ uint32_t smem_u32(const void* p) {
    uint32_t a;
    asm("{ .reg .u64 t; cvta.to.shared.u64 t, %1; cvt.u32.u64 %0, t; }"
        : "=r"(a) : "l"(p));
    return a;
}
__device__ __forceinline__ void ldm_x4(uint32_t* r, uint32_t addr) {
    asm volatile("ldmatrix.sync.aligned.m8n8.x4.shared.b16 {%0,%1,%2,%3}, [%4];"
                 : "=r"(r[0]), "=r"(r[1]), "=r"(r[2]), "=r"(r[3]) : "r"(addr));
}
__device__ __forceinline__ void mma_bf16(float* c, const uint32_t* a, const uint32_t* b) {
    asm volatile(
        "mma.sync.aligned.m16n8k16.row.col.f32.bf16.bf16.f32 "
        "{%0,%1,%2,%3}, {%4,%5,%6,%7}, {%8,%9}, {%0,%1,%2,%3};"
        : "+f"(c[0]), "+f"(c[1]), "+f"(c[2]), "+f"(c[3])
        : "r"(a[0]), "r"(a[1]), "r"(a[2]), "r"(a[3]), "r"(b[0]), "r"(b[1]));
}
#define CP_ASYNC16(sm, gm)                                                   \
    asm volatile("cp.async.cg.shared.global [%0], [%1], 16;" ::              \
                 "r"(sm), "l"(__cvta_generic_to_global(gm)))
#define CP_COMMIT() asm volatile("cp.async.commit_group;" ::: "memory")
#define CP_WAIT(n)  asm volatile("cp.async.wait_group %0;" :: "n"(n) : "memory")

// ============================================================================
// Kernel 1: zero accumulators
// ============================================================================
__global__ void zero_kernel() {
    g_absmax_bits  = 0u;
    g_wsum_abs     = 0.0f;
    g_wsum_absmask = 0.0f;
    g_wsum_maskcnt = 0.0f;
}

// ============================================================================
// Kernel 2: LN stats per row + global absmax of normalized output
// ============================================================================
__global__ __launch_bounds__(256) void ln_stats_kernel(
    const float4* __restrict__ x4, const float4* __restrict__ gamma4,
    const float4* __restrict__ beta4) {
    const int row = blockIdx.x;
    const int tid = threadIdx.x;
    float4 v = x4[(size_t)row * 256 + tid];
    float s  = v.x + v.y + v.z + v.w;
    float ss = fmaf(v.x, v.x, fmaf(v.y, v.y, fmaf(v.z, v.z, v.w * v.w)));
#pragma unroll
    for (int o = 16; o > 0; o >>= 1) {
        s  += __shfl_xor_sync(0xffffffffu, s, o);
        ss += __shfl_xor_sync(0xffffffffu, ss, o);
    }
    __shared__ float rs[8], rss[8], bc[2], rm[8];
    const int w = tid >> 5, lane = tid & 31;
    if (lane == 0) { rs[w] = s; rss[w] = ss; }
    __syncthreads();
    if (tid == 0) {
        float ts = 0.f, tss = 0.f;
#pragma unroll
        for (int i = 0; i < 8; ++i) { ts += rs[i]; tss += rss[i]; }
        float mu  = ts * (1.0f / 1024.0f);
        float var = tss * (1.0f / 1024.0f) - mu * mu;
        float rstd = rsqrtf(var + 1e-5f);
        bc[0] = mu; bc[1] = rstd;
        g_mu[row] = mu; g_rstd[row] = rstd;
    }
    __syncthreads();
    const float mu = bc[0], rstd = bc[1];
    float4 g = gamma4[tid], b = beta4[tid];
    float m0 = fabsf(fmaf((v.x - mu) * rstd, g.x, b.x));
    float m1 = fabsf(fmaf((v.y - mu) * rstd, g.y, b.y));
    float m2 = fabsf(fmaf((v.z - mu) * rstd, g.z, b.z));
    float m3 = fabsf(fmaf((v.w - mu) * rstd, g.w, b.w));
    float mm = fmaxf(fmaxf(m0, m1), fmaxf(m2, m3));
#pragma unroll
    for (int o = 16; o > 0; o >>= 1)
        mm = fmaxf(mm, __shfl_xor_sync(0xffffffffu, mm, o));
    if (lane == 0) rm[w] = mm;
    __syncthreads();
    if (tid == 0) {
        float t = rm[0];
#pragma unroll
        for (int i = 1; i < 8; ++i) t = fmaxf(t, rm[i]);
        atomicMax(&g_absmax_bits, __float_as_uint(t));
    }
}

// ============================================================================
// Kernel 3: sum |W|
// ============================================================================
__global__ __launch_bounds__(256) void wabs_kernel(const float4* __restrict__ w4) {
    float s = 0.f;
    for (int i = blockIdx.x * blockDim.x + threadIdx.x; i < (N_DIM * K_DIM / 4);
         i += gridDim.x * blockDim.x) {
        float4 v = w4[i];
        s += fabsf(v.x) + fabsf(v.y) + fabsf(v.z) + fabsf(v.w);
    }
#pragma unroll
    for (int o = 16; o > 0; o >>= 1) s += __shfl_xor_sync(0xffffffffu, s, o);
    __shared__ float rr[8];
    if ((threadIdx.x & 31) == 0) rr[threadIdx.x >> 5] = s;
    __syncthreads();
    if (threadIdx.x == 0) {
        float t = 0.f;
#pragma unroll
        for (int i = 0; i < 8; ++i) t += rr[i];
        atomicAdd(&g_wsum_abs, t);
    }
}

// ============================================================================
// Kernel 4: ternarize W -> bf16 {-1,0,+1}; reduce masked |W| sum + count
// ============================================================================
__global__ __launch_bounds__(256) void wtern_kernel(const float4* __restrict__ w4) {
    const int idx = blockIdx.x * 256 + threadIdx.x;
    const float delta = 0.7f * g_wsum_abs * (1.0f / (float)(N_DIM * K_DIM));
    float4 v = w4[idx];
    float a[4] = {v.x, v.y, v.z, v.w};
    float tf[4];
    float sa = 0.f, cnt = 0.f;
#pragma unroll
    for (int j = 0; j < 4; ++j) {
        float av = fabsf(a[j]);
        if (av > delta) {
            tf[j] = (a[j] > 0.f) ? 1.0f : -1.0f;
            sa += av; cnt += 1.0f;
        } else tf[j] = 0.0f;
    }
    __nv_bfloat162 p0 = __floats2bfloat162_rn(tf[0], tf[1]);
    __nv_bfloat162 p1 = __floats2bfloat162_rn(tf[2], tf[3]);
    uint2 pb;
    pb.x = *reinterpret_cast<uint32_t*>(&p0);
    pb.y = *reinterpret_cast<uint32_t*>(&p1);
    reinterpret_cast<uint2*>(g_tb)[idx] = pb;
#pragma unroll
    for (int o = 16; o > 0; o >>= 1) {
        sa  += __shfl_xor_sync(0xffffffffu, sa, o);
        cnt += __shfl_xor_sync(0xffffffffu, cnt, o);
    }
    __shared__ float ra[8], rc[8];
    if ((threadIdx.x & 31) == 0) { ra[threadIdx.x >> 5] = sa; rc[threadIdx.x >> 5] = cnt; }
    __syncthreads();
    if (threadIdx.x == 0) {
        float ta = 0.f, tc = 0.f;
#pragma unroll
        for (int i = 0; i < 8; ++i) { ta += ra[i]; tc += rc[i]; }
        atomicAdd(&g_wsum_absmask, ta);
        atomicAdd(&g_wsum_maskcnt, tc);
    }
}

// ============================================================================
// Kernel 5: finalize scalars
// ============================================================================
__global__ void finalize_kernel() {
    float amax  = fmaxf(__uint_as_float(g_absmax_bits), 1e-8f);
    float scale = amax * (1.0f / 127.0f);
    float alpha = g_wsum_absmask / fmaxf(g_wsum_maskcnt, 1.0f);
    g_outscale = scale * alpha;
    g_qinv     = 127.0f / amax;
}

// ============================================================================
// Kernel 6: quantize LN(x) -> bf16 integer codes in [-127,127]
// ============================================================================
__global__ __launch_bounds__(256) void quant_kernel(
    const float4* __restrict__ x4, const float4* __restrict__ gamma4,
    const float4* __restrict__ beta4) {
    const int idx = blockIdx.x * 256 + threadIdx.x;
    const int row = idx >> 8;
    const int c4  = idx & 255;
    const float mu = g_mu[row], rstd = g_rstd[row], inv = g_qinv;
    float4 v = x4[idx];
    float4 g = gamma4[c4], b = beta4[c4];
    float q0 = rintf(fminf(fmaxf(fmaf((v.x - mu) * rstd, g.x, b.x) * inv, -127.f), 127.f));
    float q1 = rintf(fminf(fmaxf(fmaf((v.y - mu) * rstd, g.y, b.y) * inv, -127.f), 127.f));
    float q2 = rintf(fminf(fmaxf(fmaf((v.z - mu) * rstd, g.z, b.z) * inv, -127.f), 127.f));
    float q3 = rintf(fminf(fmaxf(fmaf((v.w - mu) * rstd, g.w, b.w) * inv, -127.f), 127.f));
    __nv_bfloat162 p0 = __floats2bfloat162_rn(q0, q1);
    __nv_bfloat162 p1 = __floats2bfloat162_rn(q2, q3);
    uint2 pb;
    pb.x = *reinterpret_cast<uint32_t*>(&p0);
    pb.y = *reinterpret_cast<uint32_t*>(&p1);
    reinterpret_cast<uint2*>(g_qb)[idx] = pb;
}

// ============================================================================
// Kernel 7: bf16 GEMM via mma.sync m16n8k16 (HMMA), f32 accum
// CTA tile 128x128, 128 threads = 4 warps (2M x 2N), warp tile 64x64
// K chunked by 128 B (k64), 3-stage cp.async pipeline, xor-swizzled smem
// single-sync mainloop, direct-store epilogue, 2 CTAs/SM (96KB each)
// ============================================================================
#define GEMM_STAGES 3
#define STAGE_BYTES 32768
#define GEMM_SMEM   (GEMM_STAGES * STAGE_BYTES)
#define NK_CHUNKS   16

static __device__ __forceinline__ void load_stage(
    const uint8_t* __restrict__ Ag, const uint8_t* __restrict__ Bg,
    uint32_t sA, uint32_t sB, int kt, int tid) {
    const int koff = kt * 128;   // bytes
#pragma unroll
    for (int i = 0; i < 8; ++i) {    // 1024 x 16B per tile / 128 thr
        int v = i * 128 + tid;
        int row = v >> 3, c = v & 7;
        uint32_t sw = (uint32_t)(row * 128 + ((c ^ (row & 7)) << 4));
        size_t go = (size_t)row * (K_DIM * 2) + koff + c * 16;
        CP_ASYNC16(sA + sw, Ag + go);
        CP_ASYNC16(sB + sw, Bg + go);
    }
}

__global__ __launch_bounds__(128, 2) void gemm_kernel(float* __restrict__ out) {
    extern __shared__ char smem[];
    const uint32_t smem_base = smem_u32(smem);
    const int tid = threadIdx.x;
    const int wid = tid >> 5, lane = tid & 31;
    const int warp_m = wid & 1, warp_n = wid >> 1;   // 2 x 2
    const int m0 = blockIdx.y * 128, n0 = blockIdx.x * 128;

    const uint8_t* Ag = reinterpret_cast<const uint8_t*>(g_qb) + (size_t)m0 * K_DIM * 2;
    const uint8_t* Bg = reinterpret_cast<const uint8_t*>(g_tb) + (size_t)n0 * K_DIM * 2;

    load_stage(Ag, Bg, smem_base, smem_base + 16384, 0, tid);
    CP_COMMIT();
    load_stage(Ag, Bg, smem_base + STAGE_BYTES, smem_base + STAGE_BYTES + 16384, 1, tid);
    CP_COMMIT();

    float C[4][8][4];
#pragma unroll
    for (int i = 0; i < 4; ++i)
#pragma unroll
        for (int j = 0; j < 8; ++j)
#pragma unroll
            for (int k = 0; k < 4; ++k) C[i][j][k] = 0.0f;

    const int rA  = warp_m * 64 + (lane & 15);
    const int cA  = (lane >> 4);
    const int rBo = ((lane & 16) >> 1) + (lane & 7);
    const int cB  = (lane >> 3) & 1;

#pragma unroll 1
    for (int kt = 0; kt < NK_CHUNKS; ++kt) {
        CP_WAIT(1);
        __syncthreads();   // single barrier: stage (kt+2)%3's last readers
                           // finished in iter kt-1 before this barrier.
        if (kt + 2 < NK_CHUNKS) {
            uint32_t sbase = smem_base + ((kt + 2) % GEMM_STAGES) * STAGE_BYTES;
            load_stage(Ag, Bg, sbase, sbase + 16384, kt + 2, tid);
        }
        CP_COMMIT();

        const uint32_t aB = smem_base + (kt % GEMM_STAGES) * STAGE_BYTES;
        const uint32_t bB = aB + 16384;
#pragma unroll
        for (int ks = 0; ks < 4; ++ks) {         // 4 k16-steps per 128B chunk
            uint32_t a[4][4];
#pragma unroll
            for (int fm = 0; fm < 4; ++fm) {
                int row = rA + fm * 16;
                ldm_x4(a[fm], aB + row * 128 + (((ks * 2 + cA) ^ (row & 7)) << 4));
            }
            uint32_t b[4][4];
#pragma unroll
            for (int p = 0; p < 4; ++p) {
                int row = warp_n * 64 + p * 16 + rBo;
                ldm_x4(b[p], bB + row * 128 + (((ks * 2 + cB) ^ (row & 7)) << 4));
            }
#pragma unroll
            for (int fm = 0; fm < 4; ++fm)
#pragma unroll
                for (int p = 0; p < 4; ++p) {
                    mma_bf16(C[fm][2 * p],     a[fm], &b[p][0]);
                    mma_bf16(C[fm][2 * p + 1], a[fm], &b[p][2]);
                }
        }
    }

    // ---------------- epilogue: direct float2 stores -------------------------
    const float osc = g_outscale;
#pragma unroll
    for (int fm = 0; fm < 4; ++fm) {
        const int r0 = m0 + warp_m * 64 + fm * 16 + (lane >> 2);
#pragma unroll
        for (int fn = 0; fn < 8; ++fn) {
            const int col = n0 + warp_n * 64 + fn * 8 + (lane & 3) * 2;
            float2 lo, hi;
            lo.x = C[fm][fn][0] * osc;
            lo.y = C[fm][fn][1] * osc;
            hi.x = C[fm][fn][2] * osc;
            hi.y = C[fm][fn][3] * osc;
            *reinterpret_cast<float2*>(out + (size_t)r0 * N_DIM + col)       = lo;
            *reinterpret_cast<float2*>(out + (size_t)(r0 + 8) * N_DIM + col) = hi;
        }
    }
}

// ============================================================================
// Launch
// ============================================================================
extern "C" void kernel_launch(void* const* d_in, const int* in_sizes, int n_in,
                              void* d_out, int out_size) {
    const float4* x4 = (const float4*)d_in[0];
    const float4* w4 = (const float4*)d_in[1];
    const float4* g4 = (const float4*)d_in[2];
    const float4* b4 = (const float4*)d_in[3];
    float* out = (float*)d_out;

    zero_kernel<<<1, 1>>>();
    ln_stats_kernel<<<M_ROWS, 256>>>(x4, g4, b4);
    wabs_kernel<<<256, 256>>>(w4);
    wtern_kernel<<<(N_DIM * K_DIM / 4) / 256, 256>>>(w4);
    finalize_kernel<<<1, 1>>>();
    quant_kernel<<<(M_ROWS * K_DIM / 4) / 256, 256>>>(x4, g4, b4);

    static bool attr_set = false;
    if (!attr_set) {
        cudaFuncSetAttribute(gemm_kernel,
                             cudaFuncAttributeMaxDynamicSharedMemorySize, GEMM_SMEM);
        attr_set = true;
    }
    dim3 grid(N_DIM / 128, M_ROWS / 128);
    gemm_kernel<<<grid, 128, GEMM_SMEM>>>(out);
}

// round 10
// speedup vs baseline: 1.1233x; 1.0111x over previous
#include <cuda_runtime.h>
#include <cuda_bf16.h>
#include <cstdint>

// ============================================================================
// BitLinear: x[4,8192,1024] f32, W[1024,1024] f32, gamma/beta[1024]
// out = (scale_act*alpha) * (Qint @ T^T);  M=32768, K=1024, N=1024
// R10: R9 GEMM + explicit ks-level fragment double-buffer; finalize_kernel
//      folded into quant (inv) and gemm (outscale). 6 launches total.
// ============================================================================

#define M_ROWS 32768
#define K_DIM  1024
#define N_DIM  1024

// ---------------- device scratch ----------------
__device__ float         g_mu[M_ROWS];
__device__ float         g_rstd[M_ROWS];
__device__ unsigned int  g_absmax_bits;
__device__ float         g_wsum_abs;
__device__ float         g_wsum_absmask;
__device__ float         g_wsum_maskcnt;
__device__ __nv_bfloat16 g_qb[(size_t)M_ROWS * K_DIM];   // 64 MB
__device__ __nv_bfloat16 g_tb[(size_t)N_DIM * K_DIM];    // 2 MB

// ---------------- PTX helpers (baseline ISA) --------------------------------
__device__ __forceinline__ uint32_t smem_u32(const void* p) {
    uint32_t a;
    asm("{ .reg .u64 t; cvta.to.shared.u64 t, %1; cvt.u32.u64 %0, t; }"
        : "=r"(a) : "l"(p));
    return a;
}
__device__ __forceinline__ void ldm_x4(uint32_t* r, uint32_t addr) {
    asm volatile("ldmatrix.sync.aligned.m8n8.x4.shared.b16 {%0,%1,%2,%3}, [%4];"
                 : "=r"(r[0]), "=r"(r[1]), "=r"(r[2]), "=r"(r[3]) : "r"(addr));
}
__device__ __forceinline__ void mma_bf16(float* c, const uint32_t* a, const uint32_t* b) {
    asm volatile(
        "mma.sync.aligned.m16n8k16.row.col.f32.bf16.bf16.f32 "
        "{%0,%1,%2,%3}, {%4,%5,%6,%7}, {%8,%9}, {%0,%1,%2,%3};"
        : "+f"(c[0]), "+f"(c[1]), "+f"(c[2]), "+f"(c[3])
        : "r"(a[0]), "r"(a[1]), "r"(a[2]), "r"(a[3]), "r"(b[0]), "r"(b[1]));
}
#define CP_ASYNC16(sm, gm)                                                   \
    asm volatile("cp.async.cg.shared.global [%0], [%1], 16;" ::              \
                 "r"(sm), "l"(__cvta_generic_to_global(gm)))
#define CP_COMMIT() asm volatile("cp.async.commit_group;" ::: "memory")
#define CP_WAIT(n)  asm volatile("cp.async.wait_group %0;" :: "n"(n) : "memory")

// ============================================================================
// Kernel 1: zero accumulators
// ============================================================================
__global__ void zero_kernel() {
    g_absmax_bits  = 0u;
    g_wsum_abs     = 0.0f;
    g_wsum_absmask = 0.0f;
    g_wsum_maskcnt = 0.0f;
}

// ============================================================================
// Kernel 2: LN stats per row + global absmax of normalized output
// ============================================================================
__global__ __launch_bounds__(256) void ln_stats_kernel(
    const float4* __restrict__ x4, const float4* __restrict__ gamma4,
    const float4* __restrict__ beta4) {
    const int row = blockIdx.x;
    const int tid = threadIdx.x;
    float4 v = x4[(size_t)row * 256 + tid];
    float s  = v.x + v.y + v.z + v.w;
    float ss = fmaf(v.x, v.x, fmaf(v.y, v.y, fmaf(v.z, v.z, v.w * v.w)));
#pragma unroll
    for (int o = 16; o > 0; o >>= 1) {
        s  += __shfl_xor_sync(0xffffffffu, s, o);
        ss += __shfl_xor_sync(0xffffffffu, ss, o);
    }
    __shared__ float rs[8], rss[8], bc[2], rm[8];
    const int w = tid >> 5, lane = tid & 31;
    if (lane == 0) { rs[w] = s; rss[w] = ss; }
    __syncthreads();
    if (tid == 0) {
        float ts = 0.f, tss = 0.f;
#pragma unroll
        for (int i = 0; i < 8; ++i) { ts += rs[i]; tss += rss[i]; }
        float mu  = ts * (1.0f / 1024.0f);
        float var = tss * (1.0f / 1024.0f) - mu * mu;
        float rstd = rsqrtf(var + 1e-5f);
        bc[0] = mu; bc[1] = rstd;
        g_mu[row] = mu; g_rstd[row] = rstd;
    }
    __syncthreads();
    const float mu = bc[0], rstd = bc[1];
    float4 g = gamma4[tid], b = beta4[tid];
    float m0 = fabsf(fmaf((v.x - mu) * rstd, g.x, b.x));
    float m1 = fabsf(fmaf((v.y - mu) * rstd, g.y, b.y));
    float m2 = fabsf(fmaf((v.z - mu) * rstd, g.z, b.z));
    float m3 = fabsf(fmaf((v.w - mu) * rstd, g.w, b.w));
    float mm = fmaxf(fmaxf(m0, m1), fmaxf(m2, m3));
#pragma unroll
    for (int o = 16; o > 0; o >>= 1)
        mm = fmaxf(mm, __shfl_xor_sync(0xffffffffu, mm, o));
    if (lane == 0) rm[w] = mm;
    __syncthreads();
    if (tid == 0) {
        float t = rm[0];
#pragma unroll
        for (int i = 1; i < 8; ++i) t = fmaxf(t, rm[i]);
        atomicMax(&g_absmax_bits, __float_as_uint(t));
    }
}

// ============================================================================
// Kernel 3: sum |W|
// ============================================================================
__global__ __launch_bounds__(256) void wabs_kernel(const float4* __restrict__ w4) {
    float s = 0.f;
    for (int i = blockIdx.x * blockDim.x + threadIdx.x; i < (N_DIM * K_DIM / 4);
         i += gridDim.x * blockDim.x) {
        float4 v = w4[i];
        s += fabsf(v.x) + fabsf(v.y) + fabsf(v.z) + fabsf(v.w);
    }
#pragma unroll
    for (int o = 16; o > 0; o >>= 1) s += __shfl_xor_sync(0xffffffffu, s, o);
    __shared__ float rr[8];
    if ((threadIdx.x & 31) == 0) rr[threadIdx.x >> 5] = s;
    __syncthreads();
    if (threadIdx.x == 0) {
        float t = 0.f;
#pragma unroll
        for (int i = 0; i < 8; ++i) t += rr[i];
        atomicAdd(&g_wsum_abs, t);
    }
}

// ============================================================================
// Kernel 4: ternarize W -> bf16 {-1,0,+1}; reduce masked |W| sum + count
// ============================================================================
__global__ __launch_bounds__(256) void wtern_kernel(const float4* __restrict__ w4) {
    const int idx = blockIdx.x * 256 + threadIdx.x;
    const float delta = 0.7f * g_wsum_abs * (1.0f / (float)(N_DIM * K_DIM));
    float4 v = w4[idx];
    float a[4] = {v.x, v.y, v.z, v.w};
    float tf[4];
    float sa = 0.f, cnt = 0.f;
#pragma unroll
    for (int j = 0; j < 4; ++j) {
        float av = fabsf(a[j]);
        if (av > delta) {
            tf[j] = (a[j] > 0.f) ? 1.0f : -1.0f;
            sa += av; cnt += 1.0f;
        } else tf[j] = 0.0f;
    }
    __nv_bfloat162 p0 = __floats2bfloat162_rn(tf[0], tf[1]);
    __nv_bfloat162 p1 = __floats2bfloat162_rn(tf[2], tf[3]);
    uint2 pb;
    pb.x = *reinterpret_cast<uint32_t*>(&p0);
    pb.y = *reinterpret_cast<uint32_t*>(&p1);
    reinterpret_cast<uint2*>(g_tb)[idx] = pb;
#pragma unroll
    for (int o = 16; o > 0; o >>= 1) {
        sa  += __shfl_xor_sync(0xffffffffu, sa, o);
        cnt += __shfl_xor_sync(0xffffffffu, cnt, o);
    }
    __shared__ float ra[8], rc[8];
    if ((threadIdx.x & 31) == 0) { ra[threadIdx.x >> 5] = sa; rc[threadIdx.x >> 5] = cnt; }
    __syncthreads();
    if (threadIdx.x == 0) {
        float ta = 0.f, tc = 0.f;
#pragma unroll
        for (int i = 0; i < 8; ++i) { ta += ra[i]; tc += rc[i]; }
        atomicAdd(&g_wsum_absmask, ta);
        atomicAdd(&g_wsum_maskcnt, tc);
    }
}

// ============================================================================
// Kernel 5: quantize LN(x) -> bf16 integer codes (inv computed inline)
// ============================================================================
__global__ __launch_bounds__(256) void quant_kernel(
    const float4* __restrict__ x4, const float4* __restrict__ gamma4,
    const float4* __restrict__ beta4) {
    const int idx = blockIdx.x * 256 + threadIdx.x;
    const int row = idx >> 8;
    const int c4  = idx & 255;
    const float amax = fmaxf(__uint_as_float(g_absmax_bits), 1e-8f);
    const float inv  = 127.0f / amax;
    const float mu = g_mu[row], rstd = g_rstd[row];
    float4 v = x4[idx];
    float4 g = gamma4[c4], b = beta4[c4];
    float q0 = rintf(fminf(fmaxf(fmaf((v.x - mu) * rstd, g.x, b.x) * inv, -127.f), 127.f));
    float q1 = rintf(fminf(fmaxf(fmaf((v.y - mu) * rstd, g.y, b.y) * inv, -127.f), 127.f));
    float q2 = rintf(fminf(fmaxf(fmaf((v.z - mu) * rstd, g.z, b.z) * inv, -127.f), 127.f));
    float q3 = rintf(fminf(fmaxf(fmaf((v.w - mu) * rstd, g.w, b.w) * inv, -127.f), 127.f));
    __nv_bfloat162 p0 = __floats2bfloat162_rn(q0, q1);
    __nv_bfloat162 p1 = __floats2bfloat162_rn(q2, q3);
    uint2 pb;
    pb.x = *reinterpret_cast<uint32_t*>(&p0);
    pb.y = *reinterpret_cast<uint32_t*>(&p1);
    reinterpret_cast<uint2*>(g_qb)[idx] = pb;
}

// ============================================================================
// Kernel 6: bf16 GEMM via mma.sync m16n8k16 (HMMA), f32 accum
// CTA 128x128, 128 thr = 4 warps (2M x 2N), warp tile 64x64
// 3-stage cp.async, single-sync mainloop, ks-level fragment double-buffer,
// direct-store epilogue, outscale computed inline. 2 CTAs/SM.
// ============================================================================
#define GEMM_STAGES 3
#define STAGE_BYTES 32768
#define GEMM_SMEM   (GEMM_STAGES * STAGE_BYTES)
#define NK_CHUNKS   16

static __device__ __forceinline__ void load_stage(
    const uint8_t* __restrict__ Ag, const uint8_t* __restrict__ Bg,
    uint32_t sA, uint32_t sB, int kt, int tid) {
    const int koff = kt * 128;   // bytes
#pragma unroll
    for (int i = 0; i < 8; ++i) {    // 1024 x 16B per tile / 128 thr
        int v = i * 128 + tid;
        int row = v >> 3, c = v & 7;
        uint32_t sw = (uint32_t)(row * 128 + ((c ^ (row & 7)) << 4));
        size_t go = (size_t)row * (K_DIM * 2) + koff + c * 16;
        CP_ASYNC16(sA + sw, Ag + go);
        CP_ASYNC16(sB + sw, Bg + go);
    }
}

__global__ __launch_bounds__(128, 2) void gemm_kernel(float* __restrict__ out) {
    extern __shared__ char smem[];
    const uint32_t smem_base = smem_u32(smem);
    const int tid = threadIdx.x;
    const int wid = tid >> 5, lane = tid & 31;
    const int warp_m = wid & 1, warp_n = wid >> 1;   // 2 x 2
    const int m0 = blockIdx.y * 128, n0 = blockIdx.x * 128;

    // outscale computed locally (was finalize_kernel)
    const float amax = fmaxf(__uint_as_float(g_absmax_bits), 1e-8f);
    const float osc  = (amax * (1.0f / 127.0f)) *
                       (g_wsum_absmask / fmaxf(g_wsum_maskcnt, 1.0f));

    const uint8_t* Ag = reinterpret_cast<const uint8_t*>(g_qb) + (size_t)m0 * K_DIM * 2;
    const uint8_t* Bg = reinterpret_cast<const uint8_t*>(g_tb) + (size_t)n0 * K_DIM * 2;

    load_stage(Ag, Bg, smem_base, smem_base + 16384, 0, tid);
    CP_COMMIT();
    load_stage(Ag, Bg, smem_base + STAGE_BYTES, smem_base + STAGE_BYTES + 16384, 1, tid);
    CP_COMMIT();

    float C[4][8][4];
#pragma unroll
    for (int i = 0; i < 4; ++i)
#pragma unroll
        for (int j = 0; j < 8; ++j)
#pragma unroll
            for (int k = 0; k < 4; ++k) C[i][j][k] = 0.0f;

    const int rA  = warp_m * 64 + (lane & 15);
    const int cA  = (lane >> 4);
    const int rBo = ((lane & 16) >> 1) + (lane & 7);
    const int cB  = (lane >> 3) & 1;

#pragma unroll 1
    for (int kt = 0; kt < NK_CHUNKS; ++kt) {
        CP_WAIT(1);
        __syncthreads();   // single barrier: stage (kt+2)%3's last readers
                           // finished in iter kt-1 before this barrier.
        if (kt + 2 < NK_CHUNKS) {
            uint32_t sbase = smem_base + ((kt + 2) % GEMM_STAGES) * STAGE_BYTES;
            load_stage(Ag, Bg, sbase, sbase + 16384, kt + 2, tid);
        }
        CP_COMMIT();

        const uint32_t aB = smem_base + (kt % GEMM_STAGES) * STAGE_BYTES;
        const uint32_t bB = aB + 16384;

        // ks-level software pipeline: prefetch frags for ks+1 before mma(ks)
        uint32_t a[2][4][4], b[2][4][4];
#pragma unroll
        for (int fm = 0; fm < 4; ++fm) {
            int row = rA + fm * 16;
            ldm_x4(a[0][fm], aB + row * 128 + ((cA ^ (row & 7)) << 4));
        }
#pragma unroll
        for (int p = 0; p < 4; ++p) {
            int row = warp_n * 64 + p * 16 + rBo;
            ldm_x4(b[0][p], bB + row * 128 + ((cB ^ (row & 7)) << 4));
        }
#pragma unroll
        for (int ks = 0; ks < 4; ++ks) {
            const int cur = ks & 1, nxt = cur ^ 1;
            if (ks < 3) {
#pragma unroll
                for (int fm = 0; fm < 4; ++fm) {
                    int row = rA + fm * 16;
                    ldm_x4(a[nxt][fm],
                           aB + row * 128 + ((((ks + 1) * 2 + cA) ^ (row & 7)) << 4));
                }
#pragma unroll
                for (int p = 0; p < 4; ++p) {
                    int row = warp_n * 64 + p * 16 + rBo;
                    ldm_x4(b[nxt][p],
                           bB + row * 128 + ((((ks + 1) * 2 + cB) ^ (row & 7)) << 4));
                }
            }
#pragma unroll
            for (int fm = 0; fm < 4; ++fm)
#pragma unroll
                for (int p = 0; p < 4; ++p) {
                    mma_bf16(C[fm][2 * p],     a[cur][fm], &b[cur][p][0]);
                    mma_bf16(C[fm][2 * p + 1], a[cur][fm], &b[cur][p][2]);
                }
        }
    }

    // ---------------- epilogue: direct float2 stores -------------------------
#pragma unroll
    for (int fm = 0; fm < 4; ++fm) {
        const int r0 = m0 + warp_m * 64 + fm * 16 + (lane >> 2);
#pragma unroll
        for (int fn = 0; fn < 8; ++fn) {
            const int col = n0 + warp_n * 64 + fn * 8 + (lane & 3) * 2;
            float2 lo, hi;
            lo.x = C[fm][fn][0] * osc;
            lo.y = C[fm][fn][1] * osc;
            hi.x = C[fm][fn][2] * osc;
            hi.y = C[fm][fn][3] * osc;
            *reinterpret_cast<float2*>(out + (size_t)r0 * N_DIM + col)       = lo;
            *reinterpret_cast<float2*>(out + (size_t)(r0 + 8) * N_DIM + col) = hi;
        }
    }
}

// ============================================================================
// Launch
// ============================================================================
extern "C" void kernel_launch(void* const* d_in, const int* in_sizes, int n_in,
                              void* d_out, int out_size) {
    const float4* x4 = (const float4*)d_in[0];
    const float4* w4 = (const float4*)d_in[1];
    const float4* g4 = (const float4*)d_in[2];
    const float4* b4 = (const float4*)d_in[3];
    float* out = (float*)d_out;

    zero_kernel<<<1, 1>>>();
    ln_stats_kernel<<<M_ROWS, 256>>>(x4, g4, b4);
    wabs_kernel<<<256, 256>>>(w4);
    wtern_kernel<<<(N_DIM * K_DIM / 4) / 256, 256>>>(w4);
    quant_kernel<<<(M_ROWS * K_DIM / 4) / 256, 256>>>(x4, g4, b4);

    static bool attr_set = false;
    if (!attr_set) {
        cudaFuncSetAttribute(gemm_kernel,
                             cudaFuncAttributeMaxDynamicSharedMemorySize, GEMM_SMEM);
        attr_set = true;
    }
    dim3 grid(N_DIM / 128, M_ROWS / 128);
    gemm_kernel<<<grid, 128, GEMM_SMEM>>>(out);
}

// round 11
// speedup vs baseline: 1.1670x; 1.0389x over previous
#include <cuda_runtime.h>
#include <cuda_bf16.h>
#include <cstdint>

// ============================================================================
// BitLinear: x[4,8192,1024] f32, W[1024,1024] f32, gamma/beta[1024]
// out = (scale_act*alpha) * (Qint @ T^T);  M=32768, K=1024, N=1024
// R11: W pipeline folded into x pipeline. 4 launches:
//   zero -> [ln_stats + wabs] -> [quant + wtern] -> gemm
// GEMM unchanged from R10 (128x128 CTA, 4 warps 64x64, 2 CTAs/SM).
// ============================================================================

#define M_ROWS 32768
#define K_DIM  1024
#define N_DIM  1024

// ---------------- device scratch ----------------
__device__ float         g_mu[M_ROWS];
__device__ float         g_rstd[M_ROWS];
__device__ unsigned int  g_absmax_bits;
__device__ float         g_wsum_abs;
__device__ float         g_wsum_absmask;
__device__ float         g_wsum_maskcnt;
__device__ __nv_bfloat16 g_qb[(size_t)M_ROWS * K_DIM];   // 64 MB
__device__ __nv_bfloat16 g_tb[(size_t)N_DIM * K_DIM];    // 2 MB

// ---------------- PTX helpers (baseline ISA) --------------------------------
__device__ __forceinline__ uint32_t smem_u32(const void* p) {
    uint32_t a;
    asm("{ .reg .u64 t; cvta.to.shared.u64 t, %1; cvt.u32.u64 %0, t; }"
        : "=r"(a) : "l"(p));
    return a;
}
__device__ __forceinline__ void ldm_x4(uint32_t* r, uint32_t addr) {
    asm volatile("ldmatrix.sync.aligned.m8n8.x4.shared.b16 {%0,%1,%2,%3}, [%4];"
                 : "=r"(r[0]), "=r"(r[1]), "=r"(r[2]), "=r"(r[3]) : "r"(addr));
}
__device__ __forceinline__ void mma_bf16(float* c, const uint32_t* a, const uint32_t* b) {
    asm volatile(
        "mma.sync.aligned.m16n8k16.row.col.f32.bf16.bf16.f32 "
        "{%0,%1,%2,%3}, {%4,%5,%6,%7}, {%8,%9}, {%0,%1,%2,%3};"
        : "+f"(c[0]), "+f"(c[1]), "+f"(c[2]), "+f"(c[3])
        : "r"(a[0]), "r"(a[1]), "r"(a[2]), "r"(a[3]), "r"(b[0]), "r"(b[1]));
}
#define CP_ASYNC16(sm, gm)                                                   \
    asm volatile("cp.async.cg.shared.global [%0], [%1], 16;" ::              \
                 "r"(sm), "l"(__cvta_generic_to_global(gm)))
#define CP_COMMIT() asm volatile("cp.async.commit_group;" ::: "memory")
#define CP_WAIT(n)  asm volatile("cp.async.wait_group %0;" :: "n"(n) : "memory")

// ============================================================================
// Kernel 1: zero accumulators
// ============================================================================
__global__ void zero_kernel() {
    g_absmax_bits  = 0u;
    g_wsum_abs     = 0.0f;
    g_wsum_absmask = 0.0f;
    g_wsum_maskcnt = 0.0f;
}

// ============================================================================
// Kernel 2: LN stats per row + global absmax of LN output
//           + (blocks 0..1023) sum |W| over one 256-float4 chunk
// ============================================================================
__global__ __launch_bounds__(256) void ln_stats_kernel(
    const float4* __restrict__ x4, const float4* __restrict__ gamma4,
    const float4* __restrict__ beta4, const float4* __restrict__ w4) {
    const int row = blockIdx.x;
    const int tid = threadIdx.x;
    float4 v = x4[(size_t)row * 256 + tid];
    float s  = v.x + v.y + v.z + v.w;
    float ss = fmaf(v.x, v.x, fmaf(v.y, v.y, fmaf(v.z, v.z, v.w * v.w)));
#pragma unroll
    for (int o = 16; o > 0; o >>= 1) {
        s  += __shfl_xor_sync(0xffffffffu, s, o);
        ss += __shfl_xor_sync(0xffffffffu, ss, o);
    }
    __shared__ float rs[8], rss[8], bc[2], rm[8];
    const int w = tid >> 5, lane = tid & 31;
    if (lane == 0) { rs[w] = s; rss[w] = ss; }
    __syncthreads();
    if (tid == 0) {
        float ts = 0.f, tss = 0.f;
#pragma unroll
        for (int i = 0; i < 8; ++i) { ts += rs[i]; tss += rss[i]; }
        float mu  = ts * (1.0f / 1024.0f);
        float var = tss * (1.0f / 1024.0f) - mu * mu;
        float rstd = rsqrtf(var + 1e-5f);
        bc[0] = mu; bc[1] = rstd;
        g_mu[row] = mu; g_rstd[row] = rstd;
    }
    __syncthreads();
    const float mu = bc[0], rstd = bc[1];
    float4 g = gamma4[tid], b = beta4[tid];
    float m0 = fabsf(fmaf((v.x - mu) * rstd, g.x, b.x));
    float m1 = fabsf(fmaf((v.y - mu) * rstd, g.y, b.y));
    float m2 = fabsf(fmaf((v.z - mu) * rstd, g.z, b.z));
    float m3 = fabsf(fmaf((v.w - mu) * rstd, g.w, b.w));
    float mm = fmaxf(fmaxf(m0, m1), fmaxf(m2, m3));
#pragma unroll
    for (int o = 16; o > 0; o >>= 1)
        mm = fmaxf(mm, __shfl_xor_sync(0xffffffffu, mm, o));
    if (lane == 0) rm[w] = mm;
    __syncthreads();
    if (tid == 0) {
        float t = rm[0];
#pragma unroll
        for (int i = 1; i < 8; ++i) t = fmaxf(t, rm[i]);
        atomicMax(&g_absmax_bits, __float_as_uint(t));
    }

    // ---- folded wabs: blocks 0..1023 reduce |W| over chunk of 256 float4 ----
    if (row < 1024) {
        float4 wv = w4[row * 256 + tid];
        float sw = fabsf(wv.x) + fabsf(wv.y) + fabsf(wv.z) + fabsf(wv.w);
#pragma unroll
        for (int o = 16; o > 0; o >>= 1)
            sw += __shfl_xor_sync(0xffffffffu, sw, o);
        __syncthreads();                 // safe reuse of rs[]
        if (lane == 0) rs[w] = sw;
        __syncthreads();
        if (tid == 0) {
            float t = 0.f;
#pragma unroll
            for (int i = 0; i < 8; ++i) t += rs[i];
            atomicAdd(&g_wsum_abs, t);
        }
    }
}

// ============================================================================
// Kernel 3: quantize LN(x) -> bf16 codes (inv inline)
//           + (blocks 0..1023) ternarize W chunk + masked reductions
// ============================================================================
__global__ __launch_bounds__(256) void quant_kernel(
    const float4* __restrict__ x4, const float4* __restrict__ gamma4,
    const float4* __restrict__ beta4, const float4* __restrict__ w4) {
    const int idx = blockIdx.x * 256 + threadIdx.x;
    const int row = idx >> 8;
    const int c4  = idx & 255;
    const float amax = fmaxf(__uint_as_float(g_absmax_bits), 1e-8f);
    const float inv  = 127.0f / amax;
    const float mu = g_mu[row], rstd = g_rstd[row];
    float4 v = x4[idx];
    float4 g = gamma4[c4], b = beta4[c4];
    float q0 = rintf(fminf(fmaxf(fmaf((v.x - mu) * rstd, g.x, b.x) * inv, -127.f), 127.f));
    float q1 = rintf(fminf(fmaxf(fmaf((v.y - mu) * rstd, g.y, b.y) * inv, -127.f), 127.f));
    float q2 = rintf(fminf(fmaxf(fmaf((v.z - mu) * rstd, g.z, b.z) * inv, -127.f), 127.f));
    float q3 = rintf(fminf(fmaxf(fmaf((v.w - mu) * rstd, g.w, b.w) * inv, -127.f), 127.f));
    __nv_bfloat162 p0 = __floats2bfloat162_rn(q0, q1);
    __nv_bfloat162 p1 = __floats2bfloat162_rn(q2, q3);
    uint2 pb;
    pb.x = *reinterpret_cast<uint32_t*>(&p0);
    pb.y = *reinterpret_cast<uint32_t*>(&p1);
    reinterpret_cast<uint2*>(g_qb)[idx] = pb;

    // ---- folded wtern: blocks 0..1023, one chunk of 256 float4 each ---------
    if (blockIdx.x < 1024) {
        const int tid = threadIdx.x;
        const int widx = blockIdx.x * 256 + tid;
        const float delta = 0.7f * g_wsum_abs * (1.0f / (float)(N_DIM * K_DIM));
        float4 wv = w4[widx];
        float a[4] = {wv.x, wv.y, wv.z, wv.w};
        float tf[4];
        float sa = 0.f, cnt = 0.f;
#pragma unroll
        for (int j = 0; j < 4; ++j) {
            float av = fabsf(a[j]);
            if (av > delta) {
                tf[j] = (a[j] > 0.f) ? 1.0f : -1.0f;
                sa += av; cnt += 1.0f;
            } else tf[j] = 0.0f;
        }
        __nv_bfloat162 t0 = __floats2bfloat162_rn(tf[0], tf[1]);
        __nv_bfloat162 t1 = __floats2bfloat162_rn(tf[2], tf[3]);
        uint2 tb;
        tb.x = *reinterpret_cast<uint32_t*>(&t0);
        tb.y = *reinterpret_cast<uint32_t*>(&t1);
        reinterpret_cast<uint2*>(g_tb)[widx] = tb;
#pragma unroll
        for (int o = 16; o > 0; o >>= 1) {
            sa  += __shfl_xor_sync(0xffffffffu, sa, o);
            cnt += __shfl_xor_sync(0xffffffffu, cnt, o);
        }
        __shared__ float ra[8], rc[8];
        if ((tid & 31) == 0) { ra[tid >> 5] = sa; rc[tid >> 5] = cnt; }
        __syncthreads();
        if (tid == 0) {
            float ta = 0.f, tc = 0.f;
#pragma unroll
            for (int i = 0; i < 8; ++i) { ta += ra[i]; tc += rc[i]; }
            atomicAdd(&g_wsum_absmask, ta);
            atomicAdd(&g_wsum_maskcnt, tc);
        }
    }
}

// ============================================================================
// Kernel 4: bf16 GEMM via mma.sync m16n8k16 (HMMA), f32 accum — as R10
// CTA 128x128, 128 thr = 4 warps (2M x 2N), warp tile 64x64
// 3-stage cp.async, single-sync mainloop, ks-level fragment double-buffer,
// direct-store epilogue, outscale computed inline. 2 CTAs/SM.
// ============================================================================
#define GEMM_STAGES 3
#define STAGE_BYTES 32768
#define GEMM_SMEM   (GEMM_STAGES * STAGE_BYTES)
#define NK_CHUNKS   16

static __device__ __forceinline__ void load_stage(
    const uint8_t* __restrict__ Ag, const uint8_t* __restrict__ Bg,
    uint32_t sA, uint32_t sB, int kt, int tid) {
    const int koff = kt * 128;   // bytes
#pragma unroll
    for (int i = 0; i < 8; ++i) {    // 1024 x 16B per tile / 128 thr
        int v = i * 128 + tid;
        int row = v >> 3, c = v & 7;
        uint32_t sw = (uint32_t)(row * 128 + ((c ^ (row & 7)) << 4));
        size_t go = (size_t)row * (K_DIM * 2) + koff + c * 16;
        CP_ASYNC16(sA + sw, Ag + go);
        CP_ASYNC16(sB + sw, Bg + go);
    }
}

__global__ __launch_bounds__(128, 2) void gemm_kernel(float* __restrict__ out) {
    extern __shared__ char smem[];
    const uint32_t smem_base = smem_u32(smem);
    const int tid = threadIdx.x;
    const int wid = tid >> 5, lane = tid & 31;
    const int warp_m = wid & 1, warp_n = wid >> 1;   // 2 x 2
    const int m0 = blockIdx.y * 128, n0 = blockIdx.x * 128;

    const float amax = fmaxf(__uint_as_float(g_absmax_bits), 1e-8f);
    const float osc  = (amax * (1.0f / 127.0f)) *
                       (g_wsum_absmask / fmaxf(g_wsum_maskcnt, 1.0f));

    const uint8_t* Ag = reinterpret_cast<const uint8_t*>(g_qb) + (size_t)m0 * K_DIM * 2;
    const uint8_t* Bg = reinterpret_cast<const uint8_t*>(g_tb) + (size_t)n0 * K_DIM * 2;

    load_stage(Ag, Bg, smem_base, smem_base + 16384, 0, tid);
    CP_COMMIT();
    load_stage(Ag, Bg, smem_base + STAGE_BYTES, smem_base + STAGE_BYTES + 16384, 1, tid);
    CP_COMMIT();

    float C[4][8][4];
#pragma unroll
    for (int i = 0; i < 4; ++i)
#pragma unroll
        for (int j = 0; j < 8; ++j)
#pragma unroll
            for (int k = 0; k < 4; ++k) C[i][j][k] = 0.0f;

    const int rA  = warp_m * 64 + (lane & 15);
    const int cA  = (lane >> 4);
    const int rBo = ((lane & 16) >> 1) + (lane & 7);
    const int cB  = (lane >> 3) & 1;

#pragma unroll 1
    for (int kt = 0; kt < NK_CHUNKS; ++kt) {
        CP_WAIT(1);
        __syncthreads();   // single barrier: stage (kt+2)%3's last readers
                           // finished in iter kt-1 before this barrier.
        if (kt + 2 < NK_CHUNKS) {
            uint32_t sbase = smem_base + ((kt + 2) % GEMM_STAGES) * STAGE_BYTES;
            load_stage(Ag, Bg, sbase, sbase + 16384, kt + 2, tid);
        }
        CP_COMMIT();

        const uint32_t aB = smem_base + (kt % GEMM_STAGES) * STAGE_BYTES;
        const uint32_t bB = aB + 16384;

        // ks-level software pipeline: prefetch frags for ks+1 before mma(ks)
        uint32_t a[2][4][4], b[2][4][4];
#pragma unroll
        for (int fm = 0; fm < 4; ++fm) {
            int row = rA + fm * 16;
            ldm_x4(a[0][fm], aB + row * 128 + ((cA ^ (row & 7)) << 4));
        }
#pragma unroll
        for (int p = 0; p < 4; ++p) {
            int row = warp_n * 64 + p * 16 + rBo;
            ldm_x4(b[0][p], bB + row * 128 + ((cB ^ (row & 7)) << 4));
        }
#pragma unroll
        for (int ks = 0; ks < 4; ++ks) {
            const int cur = ks & 1, nxt = cur ^ 1;
            if (ks < 3) {
#pragma unroll
                for (int fm = 0; fm < 4; ++fm) {
                    int row = rA + fm * 16;
                    ldm_x4(a[nxt][fm],
                           aB + row * 128 + ((((ks + 1) * 2 + cA) ^ (row & 7)) << 4));
                }
#pragma unroll
                for (int p = 0; p < 4; ++p) {
                    int row = warp_n * 64 + p * 16 + rBo;
                    ldm_x4(b[nxt][p],
                           bB + row * 128 + ((((ks + 1) * 2 + cB) ^ (row & 7)) << 4));
                }
            }
#pragma unroll
            for (int fm = 0; fm < 4; ++fm)
#pragma unroll
                for (int p = 0; p < 4; ++p) {
                    mma_bf16(C[fm][2 * p],     a[cur][fm], &b[cur][p][0]);
                    mma_bf16(C[fm][2 * p + 1], a[cur][fm], &b[cur][p][2]);
                }
        }
    }

    // ---------------- epilogue: direct float2 stores -------------------------
#pragma unroll
    for (int fm = 0; fm < 4; ++fm) {
        const int r0 = m0 + warp_m * 64 + fm * 16 + (lane >> 2);
#pragma unroll
        for (int fn = 0; fn < 8; ++fn) {
            const int col = n0 + warp_n * 64 + fn * 8 + (lane & 3) * 2;
            float2 lo, hi;
            lo.x = C[fm][fn][0] * osc;
            lo.y = C[fm][fn][1] * osc;
            hi.x = C[fm][fn][2] * osc;
            hi.y = C[fm][fn][3] * osc;
            *reinterpret_cast<float2*>(out + (size_t)r0 * N_DIM + col)       = lo;
            *reinterpret_cast<float2*>(out + (size_t)(r0 + 8) * N_DIM + col) = hi;
        }
    }
}

// ============================================================================
// Launch: 4 kernels
// ============================================================================
extern "C" void kernel_launch(void* const* d_in, const int* in_sizes, int n_in,
                              void* d_out, int out_size) {
    const float4* x4 = (const float4*)d_in[0];
    const float4* w4 = (const float4*)d_in[1];
    const float4* g4 = (const float4*)d_in[2];
    const float4* b4 = (const float4*)d_in[3];
    float* out = (float*)d_out;

    zero_kernel<<<1, 1>>>();
    ln_stats_kernel<<<M_ROWS, 256>>>(x4, g4, b4, w4);
    quant_kernel<<<(M_ROWS * K_DIM / 4) / 256, 256>>>(x4, g4, b4, w4);

    static bool attr_set = false;
    if (!attr_set) {
        cudaFuncSetAttribute(gemm_kernel,
                             cudaFuncAttributeMaxDynamicSharedMemorySize, GEMM_SMEM);
        attr_set = true;
    }
    dim3 grid(N_DIM / 128, M_ROWS / 128);
    gemm_kernel<<<grid, 128, GEMM_SMEM>>>(out);
}

// round 12
// speedup vs baseline: 1.1932x; 1.0224x over previous
#include <cuda_runtime.h>
#include <cuda_bf16.h>
#include <cstdint>

// ============================================================================
// BitLinear: x[4,8192,1024] f32, W[1024,1024] f32, gamma/beta[1024]
// out = (scale_act*alpha) * (Qint @ T^T);  M=32768, K=1024, N=1024
// R12: GEMM -> 3 CTAs/SM (2-stage pipeline, 64KB smem/CTA, <=170 regs via
//      single-buffered B frags, launch_bounds(128,3)).
//      Elementwise -> MLP=2 restructure of ln_stats and quant.
// ============================================================================

#define M_ROWS 32768
#define K_DIM  1024
#define N_DIM  1024

// ---------------- device scratch ----------------
__device__ float         g_mu[M_ROWS];
__device__ float         g_rstd[M_ROWS];
__device__ unsigned int  g_absmax_bits;
__device__ float         g_wsum_abs;
__device__ float         g_wsum_absmask;
__device__ float         g_wsum_maskcnt;
__device__ __nv_bfloat16 g_qb[(size_t)M_ROWS * K_DIM];   // 64 MB
__device__ __nv_bfloat16 g_tb[(size_t)N_DIM * K_DIM];    // 2 MB

// ---------------- PTX helpers (baseline ISA) --------------------------------
__device__ __forceinline__ uint32_t smem_u32(const void* p) {
    uint32_t a;
    asm("{ .reg .u64 t; cvta.to.shared.u64 t, %1; cvt.u32.u64 %0, t; }"
        : "=r"(a) : "l"(p));
    return a;
}
__device__ __forceinline__ void ldm_x4(uint32_t* r, uint32_t addr) {
    asm volatile("ldmatrix.sync.aligned.m8n8.x4.shared.b16 {%0,%1,%2,%3}, [%4];"
                 : "=r"(r[0]), "=r"(r[1]), "=r"(r[2]), "=r"(r[3]) : "r"(addr));
}
__device__ __forceinline__ void mma_bf16(float* c, const uint32_t* a, const uint32_t* b) {
    asm volatile(
        "mma.sync.aligned.m16n8k16.row.col.f32.bf16.bf16.f32 "
        "{%0,%1,%2,%3}, {%4,%5,%6,%7}, {%8,%9}, {%0,%1,%2,%3};"
        : "+f"(c[0]), "+f"(c[1]), "+f"(c[2]), "+f"(c[3])
        : "r"(a[0]), "r"(a[1]), "r"(a[2]), "r"(a[3]), "r"(b[0]), "r"(b[1]));
}
#define CP_ASYNC16(sm, gm)                                                   \
    asm volatile("cp.async.cg.shared.global [%0], [%1], 16;" ::              \
                 "r"(sm), "l"(__cvta_generic_to_global(gm)))
#define CP_COMMIT() asm volatile("cp.async.commit_group;" ::: "memory")
#define CP_WAIT(n)  asm volatile("cp.async.wait_group %0;" :: "n"(n) : "memory")

// ============================================================================
// Kernel 1: zero accumulators
// ============================================================================
__global__ void zero_kernel() {
    g_absmax_bits  = 0u;
    g_wsum_abs     = 0.0f;
    g_wsum_absmask = 0.0f;
    g_wsum_maskcnt = 0.0f;
}

// ============================================================================
// Kernel 2: LN stats per row (128 thr/row, 2 float4/thread, MLP=2)
//           + global absmax; blocks 0..1023 also reduce |W| chunk
// ============================================================================
__global__ __launch_bounds__(128) void ln_stats_kernel(
    const float4* __restrict__ x4, const float4* __restrict__ gamma4,
    const float4* __restrict__ beta4, const float4* __restrict__ w4) {
    const int row = blockIdx.x;
    const int tid = threadIdx.x;
    const int w = tid >> 5, lane = tid & 31;

    float4 v1 = x4[(size_t)row * 256 + tid];
    float4 v2 = x4[(size_t)row * 256 + tid + 128];
    float s  = (v1.x + v1.y + v1.z + v1.w) + (v2.x + v2.y + v2.z + v2.w);
    float ss = fmaf(v1.x, v1.x, fmaf(v1.y, v1.y, fmaf(v1.z, v1.z, v1.w * v1.w)));
    ss = fmaf(v2.x, v2.x, fmaf(v2.y, v2.y, fmaf(v2.z, v2.z, fmaf(v2.w, v2.w, ss))));
#pragma unroll
    for (int o = 16; o > 0; o >>= 1) {
        s  += __shfl_xor_sync(0xffffffffu, s, o);
        ss += __shfl_xor_sync(0xffffffffu, ss, o);
    }
    __shared__ float rs[4], rss[4], bc[2], rm[4];
    if (lane == 0) { rs[w] = s; rss[w] = ss; }
    __syncthreads();
    if (tid == 0) {
        float ts = rs[0] + rs[1] + rs[2] + rs[3];
        float tss = rss[0] + rss[1] + rss[2] + rss[3];
        float mu  = ts * (1.0f / 1024.0f);
        float var = tss * (1.0f / 1024.0f) - mu * mu;
        float rstd = rsqrtf(var + 1e-5f);
        bc[0] = mu; bc[1] = rstd;
        g_mu[row] = mu; g_rstd[row] = rstd;
    }
    __syncthreads();
    const float mu = bc[0], rstd = bc[1];
    float4 g1 = gamma4[tid],       b1 = beta4[tid];
    float4 g2 = gamma4[tid + 128], b2 = beta4[tid + 128];
    float mm = fabsf(fmaf((v1.x - mu) * rstd, g1.x, b1.x));
    mm = fmaxf(mm, fabsf(fmaf((v1.y - mu) * rstd, g1.y, b1.y)));
    mm = fmaxf(mm, fabsf(fmaf((v1.z - mu) * rstd, g1.z, b1.z)));
    mm = fmaxf(mm, fabsf(fmaf((v1.w - mu) * rstd, g1.w, b1.w)));
    mm = fmaxf(mm, fabsf(fmaf((v2.x - mu) * rstd, g2.x, b2.x)));
    mm = fmaxf(mm, fabsf(fmaf((v2.y - mu) * rstd, g2.y, b2.y)));
    mm = fmaxf(mm, fabsf(fmaf((v2.z - mu) * rstd, g2.z, b2.z)));
    mm = fmaxf(mm, fabsf(fmaf((v2.w - mu) * rstd, g2.w, b2.w)));
#pragma unroll
    for (int o = 16; o > 0; o >>= 1)
        mm = fmaxf(mm, __shfl_xor_sync(0xffffffffu, mm, o));
    if (lane == 0) rm[w] = mm;
    __syncthreads();
    if (tid == 0)
        atomicMax(&g_absmax_bits,
                  __float_as_uint(fmaxf(fmaxf(rm[0], rm[1]), fmaxf(rm[2], rm[3]))));

    // ---- folded wabs: blocks 0..1023 reduce |W| over 256-float4 chunk ------
    if (row < 1024) {
        float4 wv1 = w4[row * 256 + tid];
        float4 wv2 = w4[row * 256 + tid + 128];
        float sw = fabsf(wv1.x) + fabsf(wv1.y) + fabsf(wv1.z) + fabsf(wv1.w)
                 + fabsf(wv2.x) + fabsf(wv2.y) + fabsf(wv2.z) + fabsf(wv2.w);
#pragma unroll
        for (int o = 16; o > 0; o >>= 1)
            sw += __shfl_xor_sync(0xffffffffu, sw, o);
        __syncthreads();
        if (lane == 0) rs[w] = sw;
        __syncthreads();
        if (tid == 0)
            atomicAdd(&g_wsum_abs, rs[0] + rs[1] + rs[2] + rs[3]);
    }
}

// ============================================================================
// Kernel 3: quantize LN(x) -> bf16 codes, 2 elements/thread (MLP=2)
//           + blocks 0..1023 ternarize W chunk + masked reductions
// ============================================================================
#define QHALF (M_ROWS * K_DIM / 4 / 2)   // 4194304 float4 per half

__global__ __launch_bounds__(256) void quant_kernel(
    const float4* __restrict__ x4, const float4* __restrict__ gamma4,
    const float4* __restrict__ beta4, const float4* __restrict__ w4) {
    const int idx = blockIdx.x * 256 + threadIdx.x;
    const int c4  = idx & 255;
    const float amax = fmaxf(__uint_as_float(g_absmax_bits), 1e-8f);
    const float inv  = 127.0f / amax;
    const int row1 = idx >> 8;
    const int row2 = row1 + (M_ROWS / 2);
    const float mu1 = g_mu[row1], rstd1 = g_rstd[row1];
    const float mu2 = g_mu[row2], rstd2 = g_rstd[row2];
    float4 v1 = x4[idx];
    float4 v2 = x4[idx + QHALF];
    float4 g = gamma4[c4], b = beta4[c4];

    float q0 = rintf(fminf(fmaxf(fmaf((v1.x - mu1) * rstd1, g.x, b.x) * inv, -127.f), 127.f));
    float q1 = rintf(fminf(fmaxf(fmaf((v1.y - mu1) * rstd1, g.y, b.y) * inv, -127.f), 127.f));
    float q2 = rintf(fminf(fmaxf(fmaf((v1.z - mu1) * rstd1, g.z, b.z) * inv, -127.f), 127.f));
    float q3 = rintf(fminf(fmaxf(fmaf((v1.w - mu1) * rstd1, g.w, b.w) * inv, -127.f), 127.f));
    float r0 = rintf(fminf(fmaxf(fmaf((v2.x - mu2) * rstd2, g.x, b.x) * inv, -127.f), 127.f));
    float r1 = rintf(fminf(fmaxf(fmaf((v2.y - mu2) * rstd2, g.y, b.y) * inv, -127.f), 127.f));
    float r2 = rintf(fminf(fmaxf(fmaf((v2.z - mu2) * rstd2, g.z, b.z) * inv, -127.f), 127.f));
    float r3 = rintf(fminf(fmaxf(fmaf((v2.w - mu2) * rstd2, g.w, b.w) * inv, -127.f), 127.f));

    __nv_bfloat162 p0 = __floats2bfloat162_rn(q0, q1);
    __nv_bfloat162 p1 = __floats2bfloat162_rn(q2, q3);
    uint2 pb;
    pb.x = *reinterpret_cast<uint32_t*>(&p0);
    pb.y = *reinterpret_cast<uint32_t*>(&p1);
    reinterpret_cast<uint2*>(g_qb)[idx] = pb;
    __nv_bfloat162 s0 = __floats2bfloat162_rn(r0, r1);
    __nv_bfloat162 s1 = __floats2bfloat162_rn(r2, r3);
    uint2 sb;
    sb.x = *reinterpret_cast<uint32_t*>(&s0);
    sb.y = *reinterpret_cast<uint32_t*>(&s1);
    reinterpret_cast<uint2*>(g_qb)[idx + QHALF] = sb;

    // ---- folded wtern: blocks 0..1023, one chunk of 256 float4 each --------
    if (blockIdx.x < 1024) {
        const int tid = threadIdx.x;
        const int widx = blockIdx.x * 256 + tid;
        const float delta = 0.7f * g_wsum_abs * (1.0f / (float)(N_DIM * K_DIM));
        float4 wv = w4[widx];
        float a[4] = {wv.x, wv.y, wv.z, wv.w};
        float tf[4];
        float sa = 0.f, cnt = 0.f;
#pragma unroll
        for (int j = 0; j < 4; ++j) {
            float av = fabsf(a[j]);
            if (av > delta) {
                tf[j] = (a[j] > 0.f) ? 1.0f : -1.0f;
                sa += av; cnt += 1.0f;
            } else tf[j] = 0.0f;
        }
        __nv_bfloat162 t0 = __floats2bfloat162_rn(tf[0], tf[1]);
        __nv_bfloat162 t1 = __floats2bfloat162_rn(tf[2], tf[3]);
        uint2 tb;
        tb.x = *reinterpret_cast<uint32_t*>(&t0);
        tb.y = *reinterpret_cast<uint32_t*>(&t1);
        reinterpret_cast<uint2*>(g_tb)[widx] = tb;
#pragma unroll
        for (int o = 16; o > 0; o >>= 1) {
            sa  += __shfl_xor_sync(0xffffffffu, sa, o);
            cnt += __shfl_xor_sync(0xffffffffu, cnt, o);
        }
        __shared__ float ra[8], rc[8];
        if ((tid & 31) == 0) { ra[tid >> 5] = sa; rc[tid >> 5] = cnt; }
        __syncthreads();
        if (tid == 0) {
            float ta = 0.f, tc = 0.f;
#pragma unroll
            for (int i = 0; i < 8; ++i) { ta += ra[i]; tc += rc[i]; }
            atomicAdd(&g_wsum_absmask, ta);
            atomicAdd(&g_wsum_maskcnt, tc);
        }
    }
}

// ============================================================================
// Kernel 4: bf16 GEMM via mma.sync m16n8k16 (HMMA), f32 accum
// CTA 128x128, 128 thr = 4 warps (2M x 2N), warp tile 64x64
// 2-stage cp.async (64KB smem), single barrier/iter, single-buffered B frags
// -> <=170 regs -> 3 CTAs/SM (12 warps). Direct-store epilogue.
// ============================================================================
#define GEMM_STAGES 2
#define STAGE_BYTES 32768
#define GEMM_SMEM   (GEMM_STAGES * STAGE_BYTES)   // 65536
#define NK_CHUNKS   16

static __device__ __forceinline__ void load_stage(
    const uint8_t* __restrict__ Ag, const uint8_t* __restrict__ Bg,
    uint32_t sA, uint32_t sB, int kt, int tid) {
    const int koff = kt * 128;   // bytes
#pragma unroll
    for (int i = 0; i < 8; ++i) {    // 1024 x 16B per tile / 128 thr
        int v = i * 128 + tid;
        int row = v >> 3, c = v & 7;
        uint32_t sw = (uint32_t)(row * 128 + ((c ^ (row & 7)) << 4));
        size_t go = (size_t)row * (K_DIM * 2) + koff + c * 16;
        CP_ASYNC16(sA + sw, Ag + go);
        CP_ASYNC16(sB + sw, Bg + go);
    }
}

__global__ __launch_bounds__(128, 3) void gemm_kernel(float* __restrict__ out) {
    extern __shared__ char smem[];
    const uint32_t smem_base = smem_u32(smem);
    const int tid = threadIdx.x;
    const int wid = tid >> 5, lane = tid & 31;
    const int warp_m = wid & 1, warp_n = wid >> 1;   // 2 x 2
    const int m0 = blockIdx.y * 128, n0 = blockIdx.x * 128;

    const float amax = fmaxf(__uint_as_float(g_absmax_bits), 1e-8f);
    const float osc  = (amax * (1.0f / 127.0f)) *
                       (g_wsum_absmask / fmaxf(g_wsum_maskcnt, 1.0f));

    const uint8_t* Ag = reinterpret_cast<const uint8_t*>(g_qb) + (size_t)m0 * K_DIM * 2;
    const uint8_t* Bg = reinterpret_cast<const uint8_t*>(g_tb) + (size_t)n0 * K_DIM * 2;

    load_stage(Ag, Bg, smem_base, smem_base + 16384, 0, tid);
    CP_COMMIT();

    float C[4][8][4];
#pragma unroll
    for (int i = 0; i < 4; ++i)
#pragma unroll
        for (int j = 0; j < 8; ++j)
#pragma unroll
            for (int k = 0; k < 4; ++k) C[i][j][k] = 0.0f;

    const int rA  = warp_m * 64 + (lane & 15);
    const int cA  = (lane >> 4);
    const int rBo = ((lane & 16) >> 1) + (lane & 7);
    const int cB  = (lane >> 3) & 1;

#pragma unroll 1
    for (int kt = 0; kt < NK_CHUNKS; ++kt) {
        __syncthreads();   // all threads done computing from buf (kt+1)&1
                           // (iter kt-1), so it's safe to overwrite it below
        if (kt + 1 < NK_CHUNKS) {
            uint32_t sbase = smem_base + ((kt + 1) & 1) * STAGE_BYTES;
            load_stage(Ag, Bg, sbase, sbase + 16384, kt + 1, tid);
        }
        CP_COMMIT();
        CP_WAIT(1);        // load(kt) complete (load(kt+1) still pending)
        __syncthreads();   // make load(kt)'s smem visible to all threads

        const uint32_t aB = smem_base + (kt & 1) * STAGE_BYTES;
        const uint32_t bB = aB + 16384;
#pragma unroll
        for (int ks = 0; ks < 4; ++ks) {
            uint32_t a[4][4];
#pragma unroll
            for (int fm = 0; fm < 4; ++fm) {
                int row = rA + fm * 16;
                ldm_x4(a[fm], aB + row * 128 + (((ks * 2 + cA) ^ (row & 7)) << 4));
            }
#pragma unroll
            for (int p = 0; p < 4; ++p) {
                uint32_t b[4];
                int row = warp_n * 64 + p * 16 + rBo;
                ldm_x4(b, bB + row * 128 + (((ks * 2 + cB) ^ (row & 7)) << 4));
#pragma unroll
                for (int fm = 0; fm < 4; ++fm) {
                    mma_bf16(C[fm][2 * p],     a[fm], &b[0]);
                    mma_bf16(C[fm][2 * p + 1], a[fm], &b[2]);
                }
            }
        }
    }

    // ---------------- epilogue: direct float2 stores -------------------------
#pragma unroll
    for (int fm = 0; fm < 4; ++fm) {
        const int r0 = m0 + warp_m * 64 + fm * 16 + (lane >> 2);
#pragma unroll
        for (int fn = 0; fn < 8; ++fn) {
            const int col = n0 + warp_n * 64 + fn * 8 + (lane & 3) * 2;
            float2 lo, hi;
            lo.x = C[fm][fn][0] * osc;
            lo.y = C[fm][fn][1] * osc;
            hi.x = C[fm][fn][2] * osc;
            hi.y = C[fm][fn][3] * osc;
            *reinterpret_cast<float2*>(out + (size_t)r0 * N_DIM + col)       = lo;
            *reinterpret_cast<float2*>(out + (size_t)(r0 + 8) * N_DIM + col) = hi;
        }
    }
}

// ============================================================================
// Launch: 4 kernels
// ============================================================================
extern "C" void kernel_launch(void* const* d_in, const int* in_sizes, int n_in,
                              void* d_out, int out_size) {
    const float4* x4 = (const float4*)d_in[0];
    const float4* w4 = (const float4*)d_in[1];
    const float4* g4 = (const float4*)d_in[2];
    const float4* b4 = (const float4*)d_in[3];
    float* out = (float*)d_out;

    zero_kernel<<<1, 1>>>();
    ln_stats_kernel<<<M_ROWS, 128>>>(x4, g4, b4, w4);
    quant_kernel<<<(M_ROWS * K_DIM / 4) / 256 / 2, 256>>>(x4, g4, b4, w4);

    static bool attr_set = false;
    if (!attr_set) {
        cudaFuncSetAttribute(gemm_kernel,
                             cudaFuncAttributeMaxDynamicSharedMemorySize, GEMM_SMEM);
        attr_set = true;
    }
    dim3 grid(N_DIM / 128, M_ROWS / 128);
    gemm_kernel<<<grid, 128, GEMM_SMEM>>>(out);
}

// round 13
// speedup vs baseline: 1.2432x; 1.0420x over previous
#include <cuda_runtime.h>
#include <cuda_bf16.h>
#include <cstdint>

// ============================================================================
// BitLinear: x[4,8192,1024] f32, W[1024,1024] f32, gamma/beta[1024]
// out = (scale_act*alpha) * (Qint @ T^T);  M=32768, K=1024, N=1024
// R13: best GEMM (R11: 3-stage, 1 barrier/iter, prefetch-2, 2 CTAs/SM,
//      measured 160.5us) + best elementwise (R12 MLP=2, ~62us).
// ============================================================================

#define M_ROWS 32768
#define K_DIM  1024
#define N_DIM  1024

// ---------------- device scratch ----------------
__device__ float         g_mu[M_ROWS];
__device__ float         g_rstd[M_ROWS];
__device__ unsigned int  g_absmax_bits;
__device__ float         g_wsum_abs;
__device__ float         g_wsum_absmask;
__device__ float         g_wsum_maskcnt;
__device__ __nv_bfloat16 g_qb[(size_t)M_ROWS * K_DIM];   // 64 MB
__device__ __nv_bfloat16 g_tb[(size_t)N_DIM * K_DIM];    // 2 MB

// ---------------- PTX helpers (baseline ISA) --------------------------------
__device__ __forceinline__ uint32_t smem_u32(const void* p) {
    uint32_t a;
    asm("{ .reg .u64 t; cvta.to.shared.u64 t, %1; cvt.u32.u64 %0, t; }"
        : "=r"(a) : "l"(p));
    return a;
}
__device__ __forceinline__ void ldm_x4(uint32_t* r, uint32_t addr) {
    asm volatile("ldmatrix.sync.aligned.m8n8.x4.shared.b16 {%0,%1,%2,%3}, [%4];"
                 : "=r"(r[0]), "=r"(r[1]), "=r"(r[2]), "=r"(r[3]) : "r"(addr));
}
__device__ __forceinline__ void mma_bf16(float* c, const uint32_t* a, const uint32_t* b) {
    asm volatile(
        "mma.sync.aligned.m16n8k16.row.col.f32.bf16.bf16.f32 "
        "{%0,%1,%2,%3}, {%4,%5,%6,%7}, {%8,%9}, {%0,%1,%2,%3};"
        : "+f"(c[0]), "+f"(c[1]), "+f"(c[2]), "+f"(c[3])
        : "r"(a[0]), "r"(a[1]), "r"(a[2]), "r"(a[3]), "r"(b[0]), "r"(b[1]));
}
#define CP_ASYNC16(sm, gm)                                                   \
    asm volatile("cp.async.cg.shared.global [%0], [%1], 16;" ::              \
                 "r"(sm), "l"(__cvta_generic_to_global(gm)))
#define CP_COMMIT() asm volatile("cp.async.commit_group;" ::: "memory")
#define CP_WAIT(n)  asm volatile("cp.async.wait_group %0;" :: "n"(n) : "memory")

// ============================================================================
// Kernel 1: zero accumulators
// ============================================================================
__global__ void zero_kernel() {
    g_absmax_bits  = 0u;
    g_wsum_abs     = 0.0f;
    g_wsum_absmask = 0.0f;
    g_wsum_maskcnt = 0.0f;
}

// ============================================================================
// Kernel 2: LN stats per row (128 thr/row, 2 float4/thread, MLP=2)
//           + global absmax; blocks 0..1023 also reduce |W| chunk
// ============================================================================
__global__ __launch_bounds__(128) void ln_stats_kernel(
    const float4* __restrict__ x4, const float4* __restrict__ gamma4,
    const float4* __restrict__ beta4, const float4* __restrict__ w4) {
    const int row = blockIdx.x;
    const int tid = threadIdx.x;
    const int w = tid >> 5, lane = tid & 31;

    float4 v1 = x4[(size_t)row * 256 + tid];
    float4 v2 = x4[(size_t)row * 256 + tid + 128];
    float s  = (v1.x + v1.y + v1.z + v1.w) + (v2.x + v2.y + v2.z + v2.w);
    float ss = fmaf(v1.x, v1.x, fmaf(v1.y, v1.y, fmaf(v1.z, v1.z, v1.w * v1.w)));
    ss = fmaf(v2.x, v2.x, fmaf(v2.y, v2.y, fmaf(v2.z, v2.z, fmaf(v2.w, v2.w, ss))));
#pragma unroll
    for (int o = 16; o > 0; o >>= 1) {
        s  += __shfl_xor_sync(0xffffffffu, s, o);
        ss += __shfl_xor_sync(0xffffffffu, ss, o);
    }
    __shared__ float rs[4], rss[4], bc[2], rm[4];
    if (lane == 0) { rs[w] = s; rss[w] = ss; }
    __syncthreads();
    if (tid == 0) {
        float ts = rs[0] + rs[1] + rs[2] + rs[3];
        float tss = rss[0] + rss[1] + rss[2] + rss[3];
        float mu  = ts * (1.0f / 1024.0f);
        float var = tss * (1.0f / 1024.0f) - mu * mu;
        float rstd = rsqrtf(var + 1e-5f);
        bc[0] = mu; bc[1] = rstd;
        g_mu[row] = mu; g_rstd[row] = rstd;
    }
    __syncthreads();
    const float mu = bc[0], rstd = bc[1];
    float4 g1 = gamma4[tid],       b1 = beta4[tid];
    float4 g2 = gamma4[tid + 128], b2 = beta4[tid + 128];
    float mm = fabsf(fmaf((v1.x - mu) * rstd, g1.x, b1.x));
    mm = fmaxf(mm, fabsf(fmaf((v1.y - mu) * rstd, g1.y, b1.y)));
    mm = fmaxf(mm, fabsf(fmaf((v1.z - mu) * rstd, g1.z, b1.z)));
    mm = fmaxf(mm, fabsf(fmaf((v1.w - mu) * rstd, g1.w, b1.w)));
    mm = fmaxf(mm, fabsf(fmaf((v2.x - mu) * rstd, g2.x, b2.x)));
    mm = fmaxf(mm, fabsf(fmaf((v2.y - mu) * rstd, g2.y, b2.y)));
    mm = fmaxf(mm, fabsf(fmaf((v2.z - mu) * rstd, g2.z, b2.z)));
    mm = fmaxf(mm, fabsf(fmaf((v2.w - mu) * rstd, g2.w, b2.w)));
#pragma unroll
    for (int o = 16; o > 0; o >>= 1)
        mm = fmaxf(mm, __shfl_xor_sync(0xffffffffu, mm, o));
    if (lane == 0) rm[w] = mm;
    __syncthreads();
    if (tid == 0)
        atomicMax(&g_absmax_bits,
                  __float_as_uint(fmaxf(fmaxf(rm[0], rm[1]), fmaxf(rm[2], rm[3]))));

    // ---- folded wabs: blocks 0..1023 reduce |W| over 256-float4 chunk ------
    if (row < 1024) {
        float4 wv1 = w4[row * 256 + tid];
        float4 wv2 = w4[row * 256 + tid + 128];
        float sw = fabsf(wv1.x) + fabsf(wv1.y) + fabsf(wv1.z) + fabsf(wv1.w)
                 + fabsf(wv2.x) + fabsf(wv2.y) + fabsf(wv2.z) + fabsf(wv2.w);
#pragma unroll
        for (int o = 16; o > 0; o >>= 1)
            sw += __shfl_xor_sync(0xffffffffu, sw, o);
        __syncthreads();
        if (lane == 0) rs[w] = sw;
        __syncthreads();
        if (tid == 0)
            atomicAdd(&g_wsum_abs, rs[0] + rs[1] + rs[2] + rs[3]);
    }
}

// ============================================================================
// Kernel 3: quantize LN(x) -> bf16 codes, 2 elements/thread (MLP=2)
//           + blocks 0..1023 ternarize W chunk + masked reductions
// ============================================================================
#define QHALF (M_ROWS * K_DIM / 4 / 2)   // 4194304 float4 per half

__global__ __launch_bounds__(256) void quant_kernel(
    const float4* __restrict__ x4, const float4* __restrict__ gamma4,
    const float4* __restrict__ beta4, const float4* __restrict__ w4) {
    const int idx = blockIdx.x * 256 + threadIdx.x;
    const int c4  = idx & 255;
    const float amax = fmaxf(__uint_as_float(g_absmax_bits), 1e-8f);
    const float inv  = 127.0f / amax;
    const int row1 = idx >> 8;
    const int row2 = row1 + (M_ROWS / 2);
    const float mu1 = g_mu[row1], rstd1 = g_rstd[row1];
    const float mu2 = g_mu[row2], rstd2 = g_rstd[row2];
    float4 v1 = x4[idx];
    float4 v2 = x4[idx + QHALF];
    float4 g = gamma4[c4], b = beta4[c4];

    float q0 = rintf(fminf(fmaxf(fmaf((v1.x - mu1) * rstd1, g.x, b.x) * inv, -127.f), 127.f));
    float q1 = rintf(fminf(fmaxf(fmaf((v1.y - mu1) * rstd1, g.y, b.y) * inv, -127.f), 127.f));
    float q2 = rintf(fminf(fmaxf(fmaf((v1.z - mu1) * rstd1, g.z, b.z) * inv, -127.f), 127.f));
    float q3 = rintf(fminf(fmaxf(fmaf((v1.w - mu1) * rstd1, g.w, b.w) * inv, -127.f), 127.f));
    float r0 = rintf(fminf(fmaxf(fmaf((v2.x - mu2) * rstd2, g.x, b.x) * inv, -127.f), 127.f));
    float r1 = rintf(fminf(fmaxf(fmaf((v2.y - mu2) * rstd2, g.y, b.y) * inv, -127.f), 127.f));
    float r2 = rintf(fminf(fmaxf(fmaf((v2.z - mu2) * rstd2, g.z, b.z) * inv, -127.f), 127.f));
    float r3 = rintf(fminf(fmaxf(fmaf((v2.w - mu2) * rstd2, g.w, b.w) * inv, -127.f), 127.f));

    __nv_bfloat162 p0 = __floats2bfloat162_rn(q0, q1);
    __nv_bfloat162 p1 = __floats2bfloat162_rn(q2, q3);
    uint2 pb;
    pb.x = *reinterpret_cast<uint32_t*>(&p0);
    pb.y = *reinterpret_cast<uint32_t*>(&p1);
    reinterpret_cast<uint2*>(g_qb)[idx] = pb;
    __nv_bfloat162 s0 = __floats2bfloat162_rn(r0, r1);
    __nv_bfloat162 s1 = __floats2bfloat162_rn(r2, r3);
    uint2 sb;
    sb.x = *reinterpret_cast<uint32_t*>(&s0);
    sb.y = *reinterpret_cast<uint32_t*>(&s1);
    reinterpret_cast<uint2*>(g_qb)[idx + QHALF] = sb;

    // ---- folded wtern: blocks 0..1023, one chunk of 256 float4 each --------
    if (blockIdx.x < 1024) {
        const int tid = threadIdx.x;
        const int widx = blockIdx.x * 256 + tid;
        const float delta = 0.7f * g_wsum_abs * (1.0f / (float)(N_DIM * K_DIM));
        float4 wv = w4[widx];
        float a[4] = {wv.x, wv.y, wv.z, wv.w};
        float tf[4];
        float sa = 0.f, cnt = 0.f;
#pragma unroll
        for (int j = 0; j < 4; ++j) {
            float av = fabsf(a[j]);
            if (av > delta) {
                tf[j] = (a[j] > 0.f) ? 1.0f : -1.0f;
                sa += av; cnt += 1.0f;
            } else tf[j] = 0.0f;
        }
        __nv_bfloat162 t0 = __floats2bfloat162_rn(tf[0], tf[1]);
        __nv_bfloat162 t1 = __floats2bfloat162_rn(tf[2], tf[3]);
        uint2 tb;
        tb.x = *reinterpret_cast<uint32_t*>(&t0);
        tb.y = *reinterpret_cast<uint32_t*>(&t1);
        reinterpret_cast<uint2*>(g_tb)[widx] = tb;
#pragma unroll
        for (int o = 16; o > 0; o >>= 1) {
            sa  += __shfl_xor_sync(0xffffffffu, sa, o);
            cnt += __shfl_xor_sync(0xffffffffu, cnt, o);
        }
        __shared__ float ra[8], rc[8];
        if ((tid & 31) == 0) { ra[tid >> 5] = sa; rc[tid >> 5] = cnt; }
        __syncthreads();
        if (tid == 0) {
            float ta = 0.f, tc = 0.f;
#pragma unroll
            for (int i = 0; i < 8; ++i) { ta += ra[i]; tc += rc[i]; }
            atomicAdd(&g_wsum_absmask, ta);
            atomicAdd(&g_wsum_maskcnt, tc);
        }
    }
}

// ============================================================================
// Kernel 4: bf16 GEMM via mma.sync m16n8k16 (HMMA), f32 accum — R11 config
// CTA 128x128, 128 thr = 4 warps (2M x 2N), warp tile 64x64
// 3-stage cp.async, single barrier/iter, prefetch-2, ks frag double-buffer,
// direct-store epilogue. 2 CTAs/SM (96KB smem each).
// ============================================================================
#define GEMM_STAGES 3
#define STAGE_BYTES 32768
#define GEMM_SMEM   (GEMM_STAGES * STAGE_BYTES)   // 98304
#define NK_CHUNKS   16

static __device__ __forceinline__ void load_stage(
    const uint8_t* __restrict__ Ag, const uint8_t* __restrict__ Bg,
    uint32_t sA, uint32_t sB, int kt, int tid) {
    const int koff = kt * 128;   // bytes
#pragma unroll
    for (int i = 0; i < 8; ++i) {    // 1024 x 16B per tile / 128 thr
        int v = i * 128 + tid;
        int row = v >> 3, c = v & 7;
        uint32_t sw = (uint32_t)(row * 128 + ((c ^ (row & 7)) << 4));
        size_t go = (size_t)row * (K_DIM * 2) + koff + c * 16;
        CP_ASYNC16(sA + sw, Ag + go);
        CP_ASYNC16(sB + sw, Bg + go);
    }
}

__global__ __launch_bounds__(128, 2) void gemm_kernel(float* __restrict__ out) {
    extern __shared__ char smem[];
    const uint32_t smem_base = smem_u32(smem);
    const int tid = threadIdx.x;
    const int wid = tid >> 5, lane = tid & 31;
    const int warp_m = wid & 1, warp_n = wid >> 1;   // 2 x 2
    const int m0 = blockIdx.y * 128, n0 = blockIdx.x * 128;

    const float amax = fmaxf(__uint_as_float(g_absmax_bits), 1e-8f);
    const float osc  = (amax * (1.0f / 127.0f)) *
                       (g_wsum_absmask / fmaxf(g_wsum_maskcnt, 1.0f));

    const uint8_t* Ag = reinterpret_cast<const uint8_t*>(g_qb) + (size_t)m0 * K_DIM * 2;
    const uint8_t* Bg = reinterpret_cast<const uint8_t*>(g_tb) + (size_t)n0 * K_DIM * 2;

    load_stage(Ag, Bg, smem_base, smem_base + 16384, 0, tid);
    CP_COMMIT();
    load_stage(Ag, Bg, smem_base + STAGE_BYTES, smem_base + STAGE_BYTES + 16384, 1, tid);
    CP_COMMIT();

    float C[4][8][4];
#pragma unroll
    for (int i = 0; i < 4; ++i)
#pragma unroll
        for (int j = 0; j < 8; ++j)
#pragma unroll
            for (int k = 0; k < 4; ++k) C[i][j][k] = 0.0f;

    const int rA  = warp_m * 64 + (lane & 15);
    const int cA  = (lane >> 4);
    const int rBo = ((lane & 16) >> 1) + (lane & 7);
    const int cB  = (lane >> 3) & 1;

#pragma unroll 1
    for (int kt = 0; kt < NK_CHUNKS; ++kt) {
        CP_WAIT(1);
        __syncthreads();   // single barrier: stage (kt+2)%3's last readers
                           // finished in iter kt-1 before this barrier.
        if (kt + 2 < NK_CHUNKS) {
            uint32_t sbase = smem_base + ((kt + 2) % GEMM_STAGES) * STAGE_BYTES;
            load_stage(Ag, Bg, sbase, sbase + 16384, kt + 2, tid);
        }
        CP_COMMIT();

        const uint32_t aB = smem_base + (kt % GEMM_STAGES) * STAGE_BYTES;
        const uint32_t bB = aB + 16384;

        // ks-level software pipeline: prefetch frags for ks+1 before mma(ks)
        uint32_t a[2][4][4], b[2][4][4];
#pragma unroll
        for (int fm = 0; fm < 4; ++fm) {
            int row = rA + fm * 16;
            ldm_x4(a[0][fm], aB + row * 128 + ((cA ^ (row & 7)) << 4));
        }
#pragma unroll
        for (int p = 0; p < 4; ++p) {
            int row = warp_n * 64 + p * 16 + rBo;
            ldm_x4(b[0][p], bB + row * 128 + ((cB ^ (row & 7)) << 4));
        }
#pragma unroll
        for (int ks = 0; ks < 4; ++ks) {
            const int cur = ks & 1, nxt = cur ^ 1;
            if (ks < 3) {
#pragma unroll
                for (int fm = 0; fm < 4; ++fm) {
                    int row = rA + fm * 16;
                    ldm_x4(a[nxt][fm],
                           aB + row * 128 + ((((ks + 1) * 2 + cA) ^ (row & 7)) << 4));
                }
#pragma unroll
                for (int p = 0; p < 4; ++p) {
                    int row = warp_n * 64 + p * 16 + rBo;
                    ldm_x4(b[nxt][p],
                           bB + row * 128 + ((((ks + 1) * 2 + cB) ^ (row & 7)) << 4));
                }
            }
#pragma unroll
            for (int fm = 0; fm < 4; ++fm)
#pragma unroll
                for (int p = 0; p < 4; ++p) {
                    mma_bf16(C[fm][2 * p],     a[cur][fm], &b[cur][p][0]);
                    mma_bf16(C[fm][2 * p + 1], a[cur][fm], &b[cur][p][2]);
                }
        }
    }

    // ---------------- epilogue: direct float2 stores -------------------------
#pragma unroll
    for (int fm = 0; fm < 4; ++fm) {
        const int r0 = m0 + warp_m * 64 + fm * 16 + (lane >> 2);
#pragma unroll
        for (int fn = 0; fn < 8; ++fn) {
            const int col = n0 + warp_n * 64 + fn * 8 + (lane & 3) * 2;
            float2 lo, hi;
            lo.x = C[fm][fn][0] * osc;
            lo.y = C[fm][fn][1] * osc;
            hi.x = C[fm][fn][2] * osc;
            hi.y = C[fm][fn][3] * osc;
            *reinterpret_cast<float2*>(out + (size_t)r0 * N_DIM + col)       = lo;
            *reinterpret_cast<float2*>(out + (size_t)(r0 + 8) * N_DIM + col) = hi;
        }
    }
}

// ============================================================================
// Launch: 4 kernels
// ============================================================================
extern "C" void kernel_launch(void* const* d_in, const int* in_sizes, int n_in,
                              void* d_out, int out_size) {
    const float4* x4 = (const float4*)d_in[0];
    const float4* w4 = (const float4*)d_in[1];
    const float4* g4 = (const float4*)d_in[2];
    const float4* b4 = (const float4*)d_in[3];
    float* out = (float*)d_out;

    zero_kernel<<<1, 1>>>();
    ln_stats_kernel<<<M_ROWS, 128>>>(x4, g4, b4, w4);
    quant_kernel<<<(M_ROWS * K_DIM / 4) / 256 / 2, 256>>>(x4, g4, b4, w4);

    static bool attr_set = false;
    if (!attr_set) {
        cudaFuncSetAttribute(gemm_kernel,
                             cudaFuncAttributeMaxDynamicSharedMemorySize, GEMM_SMEM);
        attr_set = true;
    }
    dim3 grid(N_DIM / 128, M_ROWS / 128);
    gemm_kernel<<<grid, 128, GEMM_SMEM>>>(out);
}